// round 1
// baseline (speedup 1.0000x reference)
#include <cuda_runtime.h>
#include <math.h>

#define B_  2
#define S_  2048
#define D_  2048
#define H_  8
#define HD_ 256
#define QH_COLS (H_*HD_)   // 2048

// ---- scratch (static device globals; no allocation) ----
__device__ float g_q [B_*S_*H_*HD_];   // [B*S, 2048]
__device__ float g_k [B_*S_*HD_];      // [B*S, 256]
__device__ float g_v [B_*S_*HD_];      // [B*S, 256]
__device__ float g_ao[B_*S_*H_*HD_];   // [B*S, 2048]

// =====================================================================
// SGEMM: C[M,N] = A[M,K] @ B[K,N], row-major, M mult of 128 (by),
// N mult of 128 (bx), K mult of 8. 256 threads, 128x128 tile, 8x8 micro.
// =====================================================================
__device__ __forceinline__ void sgemm_block(
    const float* __restrict__ A, const float* __restrict__ Bm,
    float* __restrict__ C, const int N, const int K,
    const int bx, const int by)
{
    __shared__ float As[2][8][132];   // transposed A tile, padded
    __shared__ float Bs[2][8][132];

    const int tid = threadIdx.x;
    const int tx  = tid & 15;
    const int ty  = tid >> 4;

    const int aRow = tid >> 1;          // 0..127
    const int aCol = (tid & 1) << 2;    // 0 or 4
    const int bRow = tid >> 5;          // 0..7
    const int bCol = (tid & 31) << 2;   // 0..124

    const float* Aptr = A  + (size_t)(by*128 + aRow)*K + aCol;
    const float* Bptr = Bm + (size_t)bRow*N + bx*128 + bCol;

    float acc[8][8];
#pragma unroll
    for (int i = 0; i < 8; ++i)
#pragma unroll
        for (int j = 0; j < 8; ++j) acc[i][j] = 0.f;

    // prologue: tile 0
    {
        float4 a4 = *(const float4*)Aptr;
        float4 b4 = *(const float4*)Bptr;
        As[0][aCol+0][aRow] = a4.x;
        As[0][aCol+1][aRow] = a4.y;
        As[0][aCol+2][aRow] = a4.z;
        As[0][aCol+3][aRow] = a4.w;
        *(float4*)&Bs[0][bRow][bCol] = b4;
    }
    __syncthreads();

    const int ntiles = K >> 3;
    for (int t = 0; t < ntiles; ++t) {
        const int cur  = t & 1;
        const bool more = (t + 1 < ntiles);
        float4 a4n, b4n;
        if (more) {
            a4n = *(const float4*)(Aptr + (t+1)*8);
            b4n = *(const float4*)(Bptr + (size_t)(t+1)*8*N);
        }
#pragma unroll
        for (int kk = 0; kk < 8; ++kk) {
            float a[8], b[8];
            *(float4*)&a[0] = *(const float4*)&As[cur][kk][(ty<<2)];
            *(float4*)&a[4] = *(const float4*)&As[cur][kk][64 + (ty<<2)];
            *(float4*)&b[0] = *(const float4*)&Bs[cur][kk][(tx<<2)];
            *(float4*)&b[4] = *(const float4*)&Bs[cur][kk][64 + (tx<<2)];
#pragma unroll
            for (int i = 0; i < 8; ++i)
#pragma unroll
                for (int j = 0; j < 8; ++j)
                    acc[i][j] = fmaf(a[i], b[j], acc[i][j]);
        }
        if (more) {
            const int nxt = cur ^ 1;
            As[nxt][aCol+0][aRow] = a4n.x;
            As[nxt][aCol+1][aRow] = a4n.y;
            As[nxt][aCol+2][aRow] = a4n.z;
            As[nxt][aCol+3][aRow] = a4n.w;
            *(float4*)&Bs[nxt][bRow][bCol] = b4n;
        }
        __syncthreads();
    }

#pragma unroll
    for (int i = 0; i < 8; ++i) {
        const int r = by*128 + ((i < 4) ? ((ty<<2) + i) : (64 + (ty<<2) + i - 4));
        float4 v0 = make_float4(acc[i][0], acc[i][1], acc[i][2], acc[i][3]);
        float4 v1 = make_float4(acc[i][4], acc[i][5], acc[i][6], acc[i][7]);
        *(float4*)&C[(size_t)r*N + bx*128 +      (tx<<2)] = v0;
        *(float4*)&C[(size_t)r*N + bx*128 + 64 + (tx<<2)] = v1;
    }
}

// fused QKV projection: bx 0..15 -> Q, 16..17 -> K, 18..19 -> V
__global__ void __launch_bounds__(256, 2) qkv_kernel(
    const float* __restrict__ X,  const float* __restrict__ Wq,
    const float* __restrict__ Wk, const float* __restrict__ Wv)
{
    const int bx = blockIdx.x, by = blockIdx.y;
    const float* Bm; float* C; int N; int bxl;
    if (bx < 16)      { Bm = Wq; C = g_q; N = 2048; bxl = bx;      }
    else if (bx < 18) { Bm = Wk; C = g_k; N = 256;  bxl = bx - 16; }
    else              { Bm = Wv; C = g_v; N = 256;  bxl = bx - 18; }
    sgemm_block(X, Bm, C, N, 2048, bxl, by);
}

__global__ void __launch_bounds__(256, 2) oproj_kernel(
    const float* __restrict__ Wo, float* __restrict__ out)
{
    sgemm_block(g_ao, Wo, out, 2048, 2048, blockIdx.x, blockIdx.y);
}

// =====================================================================
// RoPE in place on g_q (8 heads) and g_k (1 head).
// blockIdx.x = b*S + s (4096 blocks), threadIdx.x = pair index d (128)
// =====================================================================
__global__ void rope_kernel(const int* __restrict__ pos_ids)
{
    const int bs = blockIdx.x;
    const int d  = threadIdx.x;
    const int p  = pos_ids[bs];

    const double inv = exp(-((double)d / 128.0) * log(10000.0));
    const double ang = (double)p * inv;
    const float c  = (float)cos(ang);
    const float sn = (float)sin(ang);

#pragma unroll
    for (int h = 0; h < H_; ++h) {
        float* base = g_q + (size_t)bs*QH_COLS + h*HD_;
        const float x1 = base[d], x2 = base[d + 128];
        base[d]       = x1*c - x2*sn;
        base[d + 128] = x2*c + x1*sn;
    }
    float* kb = g_k + (size_t)bs*HD_;
    const float x1 = kb[d], x2 = kb[d + 128];
    kb[d]       = x1*c - x2*sn;
    kb[d + 128] = x2*c + x1*sn;
}

// =====================================================================
// Flash attention fp32. BM=64 queries, BN=64 keys, 256 threads.
// Qt/Kt transposed in smem [256][68]; Vs row-major [64][260]; Ps [64][68].
// Thread (tx,ty in 16x16): scores rows ty*4+i, cols tx*4+j;
// O cols = g*64 + tx*4 + u.
// =====================================================================
#define ATT_SMEM_FLOATS (2*256*68 + 64*260 + 64*68)
#define ATT_SMEM_BYTES  (ATT_SMEM_FLOATS * 4)

__global__ void __launch_bounds__(256, 1) attn_kernel(const int* __restrict__ amask)
{
    extern __shared__ float sm[];
    float* Qt = sm;                       // 256*68
    float* Kt = sm + 256*68;              // 256*68
    float* Vs = sm + 2*256*68;            // 64*260
    float* Ps = sm + 2*256*68 + 64*260;   // 64*68
    __shared__ int am[64];

    const int tid = threadIdx.x;
    const int tx  = tid & 15;
    const int ty  = tid >> 4;

    // largest-qt-first scheduling: bid 0..511
    const int bid = blockIdx.x;
    const int qt  = 31 - (bid >> 4);
    const int h   = bid & 7;
    const int b   = (bid >> 3) & 1;
    const int qbase = qt * 64;

    // ---- load Q tile transposed, pre-scaled by HD^-0.5 ----
    {
        const float scale = 0.0625f;   // 256^-0.5
#pragma unroll
        for (int it = 0; it < 16; ++it) {
            const int idx = tid + it*256;
            const int r = idx & 63;            // lane-contiguous rows -> no smem bank conflict
            const int c = (idx >> 6) << 2;
            const float4 f = *(const float4*)&g_q[(size_t)(b*S_ + qbase + r)*QH_COLS + h*HD_ + c];
            Qt[(c+0)*68 + r] = f.x * scale;
            Qt[(c+1)*68 + r] = f.y * scale;
            Qt[(c+2)*68 + r] = f.z * scale;
            Qt[(c+3)*68 + r] = f.w * scale;
        }
    }

    float m_i[4], l_i[4], o_acc[4][16];
#pragma unroll
    for (int i = 0; i < 4; ++i) {
        m_i[i] = -INFINITY; l_i[i] = 0.f;
#pragma unroll
        for (int c = 0; c < 16; ++c) o_acc[i][c] = 0.f;
    }

    for (int jt = 0; jt <= qt; ++jt) {
        const int kb = jt * 64;
        __syncthreads();   // previous PV done before overwriting Kt/Vs

        // ---- load K (transposed) and V (row-major) tiles ----
#pragma unroll
        for (int it = 0; it < 16; ++it) {
            const int idx = tid + it*256;
            {   const int r = idx & 63;
                const int c = (idx >> 6) << 2;
                const float4 f = *(const float4*)&g_k[(size_t)(b*S_ + kb + r)*HD_ + c];
                Kt[(c+0)*68 + r] = f.x;
                Kt[(c+1)*68 + r] = f.y;
                Kt[(c+2)*68 + r] = f.z;
                Kt[(c+3)*68 + r] = f.w;
            }
            {   const int r = idx >> 6;
                const int c = (idx & 63) << 2;
                *(float4*)&Vs[r*260 + c] = *(const float4*)&g_v[(size_t)(b*S_ + kb + r)*HD_ + c];
            }
        }
        if (tid < 64) am[tid] = amask[b*S_ + kb + tid];
        __syncthreads();

        // ---- S = (Q*scale) K^T : 4x4 microtile over 256 dims ----
        float s[4][4];
#pragma unroll
        for (int i = 0; i < 4; ++i)
#pragma unroll
            for (int j = 0; j < 4; ++j) s[i][j] = 0.f;

#pragma unroll 8
        for (int kk = 0; kk < 256; ++kk) {
            const float4 qa = *(const float4*)&Qt[kk*68 + (ty<<2)];
            const float4 kv = *(const float4*)&Kt[kk*68 + (tx<<2)];
            s[0][0] = fmaf(qa.x, kv.x, s[0][0]);
            s[0][1] = fmaf(qa.x, kv.y, s[0][1]);
            s[0][2] = fmaf(qa.x, kv.z, s[0][2]);
            s[0][3] = fmaf(qa.x, kv.w, s[0][3]);
            s[1][0] = fmaf(qa.y, kv.x, s[1][0]);
            s[1][1] = fmaf(qa.y, kv.y, s[1][1]);
            s[1][2] = fmaf(qa.y, kv.z, s[1][2]);
            s[1][3] = fmaf(qa.y, kv.w, s[1][3]);
            s[2][0] = fmaf(qa.z, kv.x, s[2][0]);
            s[2][1] = fmaf(qa.z, kv.y, s[2][1]);
            s[2][2] = fmaf(qa.z, kv.z, s[2][2]);
            s[2][3] = fmaf(qa.z, kv.w, s[2][3]);
            s[3][0] = fmaf(qa.w, kv.x, s[3][0]);
            s[3][1] = fmaf(qa.w, kv.y, s[3][1]);
            s[3][2] = fmaf(qa.w, kv.z, s[3][2]);
            s[3][3] = fmaf(qa.w, kv.w, s[3][3]);
        }

        // ---- mask + online softmax (per-row; redundant across 16 tx lanes) ----
        const bool diag = (jt == qt);
#pragma unroll
        for (int i = 0; i < 4; ++i) {
            const int qpos = qbase + (ty<<2) + i;
            float rmax = -INFINITY;
#pragma unroll
            for (int j = 0; j < 4; ++j) {
                const int kpos = kb + (tx<<2) + j;
                if ((diag && kpos > qpos) || am[(tx<<2)+j] == 0) s[i][j] = -INFINITY;
                rmax = fmaxf(rmax, s[i][j]);
            }
#pragma unroll
            for (int off = 8; off; off >>= 1)
                rmax = fmaxf(rmax, __shfl_xor_sync(0xffffffffu, rmax, off));
            const float mnew  = fmaxf(m_i[i], rmax);
            const float alpha = __expf(m_i[i] - mnew);
            m_i[i] = mnew;
            const float p0 = __expf(s[i][0] - mnew);
            const float p1 = __expf(s[i][1] - mnew);
            const float p2 = __expf(s[i][2] - mnew);
            const float p3 = __expf(s[i][3] - mnew);
            *(float4*)&Ps[((ty<<2)+i)*68 + (tx<<2)] = make_float4(p0, p1, p2, p3);
            float rsum = p0 + p1 + p2 + p3;
#pragma unroll
            for (int off = 8; off; off >>= 1)
                rsum += __shfl_xor_sync(0xffffffffu, rsum, off);
            l_i[i] = l_i[i]*alpha + rsum;
#pragma unroll
            for (int c = 0; c < 16; ++c) o_acc[i][c] *= alpha;
        }
        __syncthreads();   // Ps fully written

        // ---- O += P @ V ----
#pragma unroll 2
        for (int j = 0; j < 64; ++j) {
            const float pr0 = Ps[((ty<<2)+0)*68 + j];
            const float pr1 = Ps[((ty<<2)+1)*68 + j];
            const float pr2 = Ps[((ty<<2)+2)*68 + j];
            const float pr3 = Ps[((ty<<2)+3)*68 + j];
#pragma unroll
            for (int g = 0; g < 4; ++g) {
                const float4 v4 = *(const float4*)&Vs[j*260 + g*64 + (tx<<2)];
                o_acc[0][g*4+0] = fmaf(pr0, v4.x, o_acc[0][g*4+0]);
                o_acc[0][g*4+1] = fmaf(pr0, v4.y, o_acc[0][g*4+1]);
                o_acc[0][g*4+2] = fmaf(pr0, v4.z, o_acc[0][g*4+2]);
                o_acc[0][g*4+3] = fmaf(pr0, v4.w, o_acc[0][g*4+3]);
                o_acc[1][g*4+0] = fmaf(pr1, v4.x, o_acc[1][g*4+0]);
                o_acc[1][g*4+1] = fmaf(pr1, v4.y, o_acc[1][g*4+1]);
                o_acc[1][g*4+2] = fmaf(pr1, v4.z, o_acc[1][g*4+2]);
                o_acc[1][g*4+3] = fmaf(pr1, v4.w, o_acc[1][g*4+3]);
                o_acc[2][g*4+0] = fmaf(pr2, v4.x, o_acc[2][g*4+0]);
                o_acc[2][g*4+1] = fmaf(pr2, v4.y, o_acc[2][g*4+1]);
                o_acc[2][g*4+2] = fmaf(pr2, v4.z, o_acc[2][g*4+2]);
                o_acc[2][g*4+3] = fmaf(pr2, v4.w, o_acc[2][g*4+3]);
                o_acc[3][g*4+0] = fmaf(pr3, v4.x, o_acc[3][g*4+0]);
                o_acc[3][g*4+1] = fmaf(pr3, v4.y, o_acc[3][g*4+1]);
                o_acc[3][g*4+2] = fmaf(pr3, v4.z, o_acc[3][g*4+2]);
                o_acc[3][g*4+3] = fmaf(pr3, v4.w, o_acc[3][g*4+3]);
            }
        }
    }

    // ---- normalize and store ----
#pragma unroll
    for (int i = 0; i < 4; ++i) {
        const float inv = 1.f / l_i[i];
        const size_t row = (size_t)(b*S_ + qbase + (ty<<2) + i)*QH_COLS + h*HD_;
#pragma unroll
        for (int g = 0; g < 4; ++g) {
            float4 o4 = make_float4(o_acc[i][g*4+0]*inv, o_acc[i][g*4+1]*inv,
                                    o_acc[i][g*4+2]*inv, o_acc[i][g*4+3]*inv);
            *(float4*)&g_ao[row + g*64 + (tx<<2)] = o4;
        }
    }
}

// =====================================================================
extern "C" void kernel_launch(void* const* d_in, const int* in_sizes, int n_in,
                              void* d_out, int out_size)
{
    (void)in_sizes; (void)n_in; (void)out_size;
    const float* X   = (const float*)d_in[0];
    const int*   am  = (const int*)  d_in[1];
    const int*   pos = (const int*)  d_in[2];
    const float* Wq  = (const float*)d_in[3];
    const float* Wk  = (const float*)d_in[4];
    const float* Wv  = (const float*)d_in[5];
    const float* Wo  = (const float*)d_in[6];
    float* out = (float*)d_out;

    cudaFuncSetAttribute(attn_kernel, cudaFuncAttributeMaxDynamicSharedMemorySize,
                         ATT_SMEM_BYTES);

    qkv_kernel<<<dim3(20, 32), 256>>>(X, Wq, Wk, Wv);
    rope_kernel<<<B_*S_, 128>>>(pos);
    attn_kernel<<<512, 256, ATT_SMEM_BYTES>>>(am);
    oproj_kernel<<<dim3(16, 32), 256>>>(Wo, out);
}

// round 3
// speedup vs baseline: 1.4307x; 1.4307x over previous
#include <cuda_runtime.h>
#include <cuda_bf16.h>
#include <stdint.h>
#include <cstdint>
#include <math.h>

#define B_  2
#define S_  2048
#define D_  2048
#define H_  8
#define HD_ 256
#define NQKV 2560          // 2048 Q + 256 K + 256 V
#define KOFF 2048
#define VOFF 2304

// ---- scratch (static device globals; no allocation) ----
__device__ float g_qkv[B_*S_*NQKV];     // [4096, 2560] fp32 (Q|K|V)
__device__ float g_ao [B_*S_*D_];       // [4096, 2048] fp32

__device__ __nv_bfloat16 g_Xhi [B_*S_*D_];
__device__ __nv_bfloat16 g_Xlo [B_*S_*D_];
__device__ __nv_bfloat16 g_Whi [D_*NQKV];
__device__ __nv_bfloat16 g_Wlo [D_*NQKV];
__device__ __nv_bfloat16 g_WOhi[D_*D_];
__device__ __nv_bfloat16 g_WOlo[D_*D_];
__device__ __nv_bfloat16 g_AOhi[B_*S_*D_];
__device__ __nv_bfloat16 g_AOlo[B_*S_*D_];

// =====================================================================
// helpers
// =====================================================================
__device__ __forceinline__ unsigned sptr(const void* p) {
    return (unsigned)__cvta_generic_to_shared(p);
}
__device__ __forceinline__ void cpa16(void* dst, const void* src) {
    asm volatile("cp.async.cg.shared.global [%0], [%1], 16;\n"
                 :: "r"(sptr(dst)), "l"(src));
}
#define CP_COMMIT() asm volatile("cp.async.commit_group;\n")
#define CP_WAIT(N)  asm volatile("cp.async.wait_group %0;\n" :: "n"(N))

__device__ __forceinline__ void ldsm_x4(unsigned* r, unsigned a) {
    asm volatile("ldmatrix.sync.aligned.m8n8.x4.shared.b16 {%0,%1,%2,%3},[%4];"
                 : "=r"(r[0]), "=r"(r[1]), "=r"(r[2]), "=r"(r[3]) : "r"(a));
}
__device__ __forceinline__ void ldsm_x2t(unsigned* r, unsigned a) {
    asm volatile("ldmatrix.sync.aligned.m8n8.x2.trans.shared.b16 {%0,%1},[%2];"
                 : "=r"(r[0]), "=r"(r[1]) : "r"(a));
}
__device__ __forceinline__ void mma_bf16(float* d, const unsigned* a, const unsigned* b) {
    asm volatile("mma.sync.aligned.m16n8k16.row.col.f32.bf16.bf16.f32 "
                 "{%0,%1,%2,%3},{%4,%5,%6,%7},{%8,%9},{%0,%1,%2,%3};"
                 : "+f"(d[0]), "+f"(d[1]), "+f"(d[2]), "+f"(d[3])
                 : "r"(a[0]), "r"(a[1]), "r"(a[2]), "r"(a[3]),
                   "r"(b[0]), "r"(b[1]));
}
__device__ __forceinline__ void split1(float x, __nv_bfloat16& h, __nv_bfloat16& l) {
    h = __float2bfloat16(x);
    l = __float2bfloat16(x - __bfloat162float(h));
}

// =====================================================================
// split kernels: fp32 -> (hi, lo) bf16
// =====================================================================
__global__ void split_kernel(const float* __restrict__ src,
                             __nv_bfloat16* __restrict__ hi,
                             __nv_bfloat16* __restrict__ lo, int n)
{
    int i = blockIdx.x * 256 + threadIdx.x;
    if (i < n) { __nv_bfloat16 h, l; split1(src[i], h, l); hi[i] = h; lo[i] = l; }
}

__global__ void split_wqkv_kernel(const float* __restrict__ Wq,
                                  const float* __restrict__ Wk,
                                  const float* __restrict__ Wv)
{
    int i = blockIdx.x * 256 + threadIdx.x;           // over 2048*2560
    const int row = i / NQKV, col = i % NQKV;
    float x;
    if (col < KOFF)       x = Wq[row * (H_*HD_) + col];
    else if (col < VOFF)  x = Wk[row * HD_ + (col - KOFF)];
    else                  x = Wv[row * HD_ + (col - VOFF)];
    __nv_bfloat16 h, l; split1(x, h, l);
    g_Whi[i] = h; g_Wlo[i] = l;
}

// =====================================================================
// bf16x3 tensor-core GEMM: C[M,N] = A[M,K] @ B[K,N], fp32 out
// block 128x128, K-step 32, 256 threads (8 warps of 64x32), cp.async x2
// =====================================================================
#define ASi(buf,hh,r,c) (((((buf)*2 + (hh))*128 + (r))*40) + (c))
#define BSi(buf,hh,r,c) (((((buf)*2 + (hh))*32  + (r))*136) + (c))
#define GEMM_SMEM_BYTES (40960 + 34816)   // As[2][2][128][40] + Bs[2][2][32][136]

__device__ __forceinline__ void gemm_load_stage(
    __nv_bfloat16* As, __nv_bfloat16* Bs,
    const __nv_bfloat16* Ahi, const __nv_bfloat16* Alo,
    const __nv_bfloat16* Bhi, const __nv_bfloat16* Blo,
    int N, int K, int brow, int bcol, int tid, int t, int buf)
{
    const int k0 = t * 32;
#pragma unroll
    for (int h = 0; h < 2; ++h) {
        const __nv_bfloat16* Ag = h ? Alo : Ahi;
        const __nv_bfloat16* Bg = h ? Blo : Bhi;
#pragma unroll
        for (int i = 0; i < 2; ++i) {
            const int idx = tid + i * 256;
            const int ra = idx >> 2,  ca = (idx & 3) << 3;
            cpa16(&As[ASi(buf, h, ra, ca)],
                  Ag + (size_t)(brow + ra) * K + k0 + ca);
            const int rb = idx >> 4,  cb = (idx & 15) << 3;
            cpa16(&Bs[BSi(buf, h, rb, cb)],
                  Bg + (size_t)(k0 + rb) * N + bcol + cb);
        }
    }
}

__global__ void __launch_bounds__(256) mma_gemm_kernel(
    const __nv_bfloat16* __restrict__ Ahi, const __nv_bfloat16* __restrict__ Alo,
    const __nv_bfloat16* __restrict__ Bhi, const __nv_bfloat16* __restrict__ Blo,
    float* __restrict__ C, const int N, const int K)
{
    extern __shared__ __align__(16) char smem_raw[];
    __nv_bfloat16* As = (__nv_bfloat16*)(smem_raw);
    __nv_bfloat16* Bs = (__nv_bfloat16*)(smem_raw + 40960);

    const int tid  = threadIdx.x;
    const int brow = blockIdx.y * 128;
    const int bcol = blockIdx.x * 128;
    const int lane = tid & 31;
    const int warp = tid >> 5;
    const int wm   = (warp >> 2) * 64;
    const int wn   = (warp & 3) * 32;

    float acc[4][4][4];
#pragma unroll
    for (int i = 0; i < 4; ++i)
#pragma unroll
        for (int j = 0; j < 4; ++j)
#pragma unroll
            for (int u = 0; u < 4; ++u) acc[i][j][u] = 0.f;

    const int ntiles = K >> 5;
    gemm_load_stage(As, Bs, Ahi, Alo, Bhi, Blo, N, K, brow, bcol, tid, 0, 0);
    CP_COMMIT();

    for (int t = 0; t < ntiles; ++t) {
        if (t + 1 < ntiles) {
            gemm_load_stage(As, Bs, Ahi, Alo, Bhi, Blo, N, K, brow, bcol, tid,
                            t + 1, (t + 1) & 1);
            CP_COMMIT();
            CP_WAIT(1);
        } else {
            CP_WAIT(0);
        }
        __syncthreads();
        const int buf = t & 1;

#pragma unroll
        for (int ks = 0; ks < 32; ks += 16) {
            unsigned bh[4][2], bl[4][2];
#pragma unroll
            for (int nt = 0; nt < 4; ++nt) {
                ldsm_x2t(bh[nt], sptr(&Bs[BSi(buf, 0, ks + (lane & 15), wn + nt*8)]));
                ldsm_x2t(bl[nt], sptr(&Bs[BSi(buf, 1, ks + (lane & 15), wn + nt*8)]));
            }
#pragma unroll
            for (int mt = 0; mt < 4; ++mt) {
                unsigned ah[4], al[4];
                const int ar = wm + mt*16 + (lane & 15);
                const int ac = ks + ((lane >> 4) << 3);
                ldsm_x4(ah, sptr(&As[ASi(buf, 0, ar, ac)]));
                ldsm_x4(al, sptr(&As[ASi(buf, 1, ar, ac)]));
#pragma unroll
                for (int nt = 0; nt < 4; ++nt) {
                    mma_bf16(acc[mt][nt], ah, bh[nt]);
                    mma_bf16(acc[mt][nt], ah, bl[nt]);
                    mma_bf16(acc[mt][nt], al, bh[nt]);
                }
            }
        }
        __syncthreads();
    }

    // epilogue
#pragma unroll
    for (int mt = 0; mt < 4; ++mt) {
#pragma unroll
        for (int nt = 0; nt < 4; ++nt) {
            const int r0 = brow + wm + mt*16 + (lane >> 2);
            const int c0 = bcol + wn + nt*8 + ((lane & 3) << 1);
            *(float2*)&C[(size_t)r0 * N + c0]       = make_float2(acc[mt][nt][0], acc[mt][nt][1]);
            *(float2*)&C[(size_t)(r0 + 8) * N + c0] = make_float2(acc[mt][nt][2], acc[mt][nt][3]);
        }
    }
}

// =====================================================================
// RoPE in place on g_qkv (8 Q heads + 1 K head).
// =====================================================================
__global__ void rope_kernel(const int* __restrict__ pos_ids)
{
    const int bs = blockIdx.x;
    const int d  = threadIdx.x;
    const int p  = pos_ids[bs];

    const double inv = exp(-((double)d / 128.0) * log(10000.0));
    const double ang = (double)p * inv;
    const float c  = (float)cos(ang);
    const float sn = (float)sin(ang);

    float* row = g_qkv + (size_t)bs * NQKV;
#pragma unroll
    for (int h = 0; h < H_; ++h) {
        float* base = row + h * HD_;
        const float x1 = base[d], x2 = base[d + 128];
        base[d]       = x1 * c - x2 * sn;
        base[d + 128] = x2 * c + x1 * sn;
    }
    float* kb = row + KOFF;
    const float x1 = kb[d], x2 = kb[d + 128];
    kb[d]       = x1 * c - x2 * sn;
    kb[d + 128] = x2 * c + x1 * sn;
}

// =====================================================================
// Flash attention fp32
// =====================================================================
#define ATT_SMEM_FLOATS (2*256*68 + 64*260 + 64*68)
#define ATT_SMEM_BYTES  (ATT_SMEM_FLOATS * 4)

__global__ void __launch_bounds__(256, 1) attn_kernel(const int* __restrict__ amask)
{
    extern __shared__ float sm[];
    float* Qt = sm;                       // 256*68
    float* Kt = sm + 256*68;              // 256*68
    float* Vs = sm + 2*256*68;            // 64*260
    float* Ps = sm + 2*256*68 + 64*260;   // 64*68
    __shared__ int am[64];

    const int tid = threadIdx.x;
    const int tx  = tid & 15;
    const int ty  = tid >> 4;

    const int bid = blockIdx.x;
    const int qt  = 31 - (bid >> 4);
    const int h   = bid & 7;
    const int b   = (bid >> 3) & 1;
    const int qbase = qt * 64;

    {
        const float scale = 0.0625f;
#pragma unroll
        for (int it = 0; it < 16; ++it) {
            const int idx = tid + it*256;
            const int r = idx & 63;
            const int c = (idx >> 6) << 2;
            const float4 f = *(const float4*)&g_qkv[(size_t)(b*S_ + qbase + r)*NQKV + h*HD_ + c];
            Qt[(c+0)*68 + r] = f.x * scale;
            Qt[(c+1)*68 + r] = f.y * scale;
            Qt[(c+2)*68 + r] = f.z * scale;
            Qt[(c+3)*68 + r] = f.w * scale;
        }
    }

    float m_i[4], l_i[4], o_acc[4][16];
#pragma unroll
    for (int i = 0; i < 4; ++i) {
        m_i[i] = -INFINITY; l_i[i] = 0.f;
#pragma unroll
        for (int c = 0; c < 16; ++c) o_acc[i][c] = 0.f;
    }

    for (int jt = 0; jt <= qt; ++jt) {
        const int kb = jt * 64;
        __syncthreads();

#pragma unroll
        for (int it = 0; it < 16; ++it) {
            const int idx = tid + it*256;
            {   const int r = idx & 63;
                const int c = (idx >> 6) << 2;
                const float4 f = *(const float4*)&g_qkv[(size_t)(b*S_ + kb + r)*NQKV + KOFF + c];
                Kt[(c+0)*68 + r] = f.x;
                Kt[(c+1)*68 + r] = f.y;
                Kt[(c+2)*68 + r] = f.z;
                Kt[(c+3)*68 + r] = f.w;
            }
            {   const int r = idx >> 6;
                const int c = (idx & 63) << 2;
                *(float4*)&Vs[r*260 + c] = *(const float4*)&g_qkv[(size_t)(b*S_ + kb + r)*NQKV + VOFF + c];
            }
        }
        if (tid < 64) am[tid] = amask[b*S_ + kb + tid];
        __syncthreads();

        float s[4][4];
#pragma unroll
        for (int i = 0; i < 4; ++i)
#pragma unroll
            for (int j = 0; j < 4; ++j) s[i][j] = 0.f;

#pragma unroll 8
        for (int kk = 0; kk < 256; ++kk) {
            const float4 qa = *(const float4*)&Qt[kk*68 + (ty<<2)];
            const float4 kv = *(const float4*)&Kt[kk*68 + (tx<<2)];
            s[0][0] = fmaf(qa.x, kv.x, s[0][0]);
            s[0][1] = fmaf(qa.x, kv.y, s[0][1]);
            s[0][2] = fmaf(qa.x, kv.z, s[0][2]);
            s[0][3] = fmaf(qa.x, kv.w, s[0][3]);
            s[1][0] = fmaf(qa.y, kv.x, s[1][0]);
            s[1][1] = fmaf(qa.y, kv.y, s[1][1]);
            s[1][2] = fmaf(qa.y, kv.z, s[1][2]);
            s[1][3] = fmaf(qa.y, kv.w, s[1][3]);
            s[2][0] = fmaf(qa.z, kv.x, s[2][0]);
            s[2][1] = fmaf(qa.z, kv.y, s[2][1]);
            s[2][2] = fmaf(qa.z, kv.z, s[2][2]);
            s[2][3] = fmaf(qa.z, kv.w, s[2][3]);
            s[3][0] = fmaf(qa.w, kv.x, s[3][0]);
            s[3][1] = fmaf(qa.w, kv.y, s[3][1]);
            s[3][2] = fmaf(qa.w, kv.z, s[3][2]);
            s[3][3] = fmaf(qa.w, kv.w, s[3][3]);
        }

        const bool diag = (jt == qt);
#pragma unroll
        for (int i = 0; i < 4; ++i) {
            const int qpos = qbase + (ty<<2) + i;
            float rmax = -INFINITY;
#pragma unroll
            for (int j = 0; j < 4; ++j) {
                const int kpos = kb + (tx<<2) + j;
                if ((diag && kpos > qpos) || am[(tx<<2)+j] == 0) s[i][j] = -INFINITY;
                rmax = fmaxf(rmax, s[i][j]);
            }
#pragma unroll
            for (int off = 8; off; off >>= 1)
                rmax = fmaxf(rmax, __shfl_xor_sync(0xffffffffu, rmax, off));
            const float mnew  = fmaxf(m_i[i], rmax);
            const float alpha = __expf(m_i[i] - mnew);
            m_i[i] = mnew;
            const float p0 = __expf(s[i][0] - mnew);
            const float p1 = __expf(s[i][1] - mnew);
            const float p2 = __expf(s[i][2] - mnew);
            const float p3 = __expf(s[i][3] - mnew);
            *(float4*)&Ps[((ty<<2)+i)*68 + (tx<<2)] = make_float4(p0, p1, p2, p3);
            float rsum = p0 + p1 + p2 + p3;
#pragma unroll
            for (int off = 8; off; off >>= 1)
                rsum += __shfl_xor_sync(0xffffffffu, rsum, off);
            l_i[i] = l_i[i]*alpha + rsum;
#pragma unroll
            for (int c = 0; c < 16; ++c) o_acc[i][c] *= alpha;
        }
        __syncthreads();

#pragma unroll 2
        for (int j = 0; j < 64; ++j) {
            const float pr0 = Ps[((ty<<2)+0)*68 + j];
            const float pr1 = Ps[((ty<<2)+1)*68 + j];
            const float pr2 = Ps[((ty<<2)+2)*68 + j];
            const float pr3 = Ps[((ty<<2)+3)*68 + j];
#pragma unroll
            for (int g = 0; g < 4; ++g) {
                const float4 v4 = *(const float4*)&Vs[j*260 + g*64 + (tx<<2)];
                o_acc[0][g*4+0] = fmaf(pr0, v4.x, o_acc[0][g*4+0]);
                o_acc[0][g*4+1] = fmaf(pr0, v4.y, o_acc[0][g*4+1]);
                o_acc[0][g*4+2] = fmaf(pr0, v4.z, o_acc[0][g*4+2]);
                o_acc[0][g*4+3] = fmaf(pr0, v4.w, o_acc[0][g*4+3]);
                o_acc[1][g*4+0] = fmaf(pr1, v4.x, o_acc[1][g*4+0]);
                o_acc[1][g*4+1] = fmaf(pr1, v4.y, o_acc[1][g*4+1]);
                o_acc[1][g*4+2] = fmaf(pr1, v4.z, o_acc[1][g*4+2]);
                o_acc[1][g*4+3] = fmaf(pr1, v4.w, o_acc[1][g*4+3]);
                o_acc[2][g*4+0] = fmaf(pr2, v4.x, o_acc[2][g*4+0]);
                o_acc[2][g*4+1] = fmaf(pr2, v4.y, o_acc[2][g*4+1]);
                o_acc[2][g*4+2] = fmaf(pr2, v4.z, o_acc[2][g*4+2]);
                o_acc[2][g*4+3] = fmaf(pr2, v4.w, o_acc[2][g*4+3]);
                o_acc[3][g*4+0] = fmaf(pr3, v4.x, o_acc[3][g*4+0]);
                o_acc[3][g*4+1] = fmaf(pr3, v4.y, o_acc[3][g*4+1]);
                o_acc[3][g*4+2] = fmaf(pr3, v4.z, o_acc[3][g*4+2]);
                o_acc[3][g*4+3] = fmaf(pr3, v4.w, o_acc[3][g*4+3]);
            }
        }
    }

#pragma unroll
    for (int i = 0; i < 4; ++i) {
        const float inv = 1.f / l_i[i];
        const size_t row = (size_t)(b*S_ + qbase + (ty<<2) + i)*D_ + h*HD_;
#pragma unroll
        for (int g = 0; g < 4; ++g) {
            float4 o4 = make_float4(o_acc[i][g*4+0]*inv, o_acc[i][g*4+1]*inv,
                                    o_acc[i][g*4+2]*inv, o_acc[i][g*4+3]*inv);
            *(float4*)&g_ao[row + g*64 + (tx<<2)] = o4;
        }
    }
}

// =====================================================================
extern "C" void kernel_launch(void* const* d_in, const int* in_sizes, int n_in,
                              void* d_out, int out_size)
{
    (void)in_sizes; (void)n_in; (void)out_size;
    const float* X   = (const float*)d_in[0];
    const int*   am  = (const int*)  d_in[1];
    const int*   pos = (const int*)  d_in[2];
    const float* Wq  = (const float*)d_in[3];
    const float* Wk  = (const float*)d_in[4];
    const float* Wv  = (const float*)d_in[5];
    const float* Wo  = (const float*)d_in[6];
    float* out = (float*)d_out;

    cudaFuncSetAttribute(attn_kernel, cudaFuncAttributeMaxDynamicSharedMemorySize,
                         ATT_SMEM_BYTES);
    cudaFuncSetAttribute(mma_gemm_kernel, cudaFuncAttributeMaxDynamicSharedMemorySize,
                         GEMM_SMEM_BYTES);

    __nv_bfloat16 *Xhi = 0, *Xlo = 0, *Whi = 0, *Wlo = 0;
    __nv_bfloat16 *WOhi = 0, *WOlo = 0, *AOhi = 0, *AOlo = 0;
    float *qkv = 0, *ao = 0;
    cudaGetSymbolAddress((void**)&Xhi,  g_Xhi);
    cudaGetSymbolAddress((void**)&Xlo,  g_Xlo);
    cudaGetSymbolAddress((void**)&Whi,  g_Whi);
    cudaGetSymbolAddress((void**)&Wlo,  g_Wlo);
    cudaGetSymbolAddress((void**)&WOhi, g_WOhi);
    cudaGetSymbolAddress((void**)&WOlo, g_WOlo);
    cudaGetSymbolAddress((void**)&AOhi, g_AOhi);
    cudaGetSymbolAddress((void**)&AOlo, g_AOlo);
    cudaGetSymbolAddress((void**)&qkv,  g_qkv);
    cudaGetSymbolAddress((void**)&ao,   g_ao);

    const int nX  = B_*S_*D_;
    const int nW  = D_*NQKV;
    const int nWO = D_*D_;

    // 1. split inputs to bf16 hi/lo
    split_kernel<<<nX/256, 256>>>(X, Xhi, Xlo, nX);
    split_wqkv_kernel<<<nW/256, 256>>>(Wq, Wk, Wv);
    split_kernel<<<nWO/256, 256>>>(Wo, WOhi, WOlo, nWO);

    // 2. fused QKV projection: [4096,2048] @ [2048,2560] -> g_qkv
    mma_gemm_kernel<<<dim3(NQKV/128, (B_*S_)/128), 256, GEMM_SMEM_BYTES>>>(
        Xhi, Xlo, Whi, Wlo, qkv, NQKV, D_);

    // 3. RoPE
    rope_kernel<<<B_*S_, 128>>>(pos);

    // 4. flash attention
    attn_kernel<<<512, 256, ATT_SMEM_BYTES>>>(am);

    // 5. split attention output, output projection
    split_kernel<<<nX/256, 256>>>(ao, AOhi, AOlo, nX);
    mma_gemm_kernel<<<dim3(D_/128, (B_*S_)/128), 256, GEMM_SMEM_BYTES>>>(
        AOhi, AOlo, WOhi, WOlo, out, D_, D_);
}

// round 4
// speedup vs baseline: 2.4456x; 1.7094x over previous
#include <cuda_runtime.h>
#include <cuda_bf16.h>
#include <stdint.h>
#include <cstdint>
#include <math.h>

#define B_  2
#define S_  2048
#define D_  2048
#define H_  8
#define HD_ 256
#define NQKV 2560          // 2048 Q + 256 K + 256 V
#define KOFF 2048
#define VOFF 2304

// ---- scratch (static device globals; no allocation) ----
__device__ float g_qkv[B_*S_*NQKV];     // [4096, 2560] fp32 (Q|K|V)
__device__ float g_ao [B_*S_*D_];       // [4096, 2048] fp32

__device__ __nv_bfloat16 g_Xhi [B_*S_*D_];
__device__ __nv_bfloat16 g_Xlo [B_*S_*D_];
__device__ __nv_bfloat16 g_Whi [D_*NQKV];
__device__ __nv_bfloat16 g_Wlo [D_*NQKV];
__device__ __nv_bfloat16 g_WOhi[D_*D_];
__device__ __nv_bfloat16 g_WOlo[D_*D_];
__device__ __nv_bfloat16 g_AOhi[B_*S_*D_];
__device__ __nv_bfloat16 g_AOlo[B_*S_*D_];

// attention operands (bf16 hi/lo), written by rope_split
__device__ __nv_bfloat16 g_Qhi [B_*S_*D_];        // [4096][2048], pre-scaled
__device__ __nv_bfloat16 g_Qlo [B_*S_*D_];
__device__ __nv_bfloat16 g_KThi[B_*HD_*S_];       // [b][hd 256][S 2048]  (K^T)
__device__ __nv_bfloat16 g_KTlo[B_*HD_*S_];
__device__ __nv_bfloat16 g_Vhi [B_*S_*HD_];       // [4096][256]
__device__ __nv_bfloat16 g_Vlo [B_*S_*HD_];

// =====================================================================
// helpers
// =====================================================================
__device__ __forceinline__ unsigned sptr(const void* p) {
    return (unsigned)__cvta_generic_to_shared(p);
}
__device__ __forceinline__ void cpa16(void* dst, const void* src) {
    asm volatile("cp.async.cg.shared.global [%0], [%1], 16;\n"
                 :: "r"(sptr(dst)), "l"(src));
}
#define CP_COMMIT() asm volatile("cp.async.commit_group;\n")
#define CP_WAIT(N)  asm volatile("cp.async.wait_group %0;\n" :: "n"(N))

__device__ __forceinline__ void ldsm_x4(unsigned* r, unsigned a) {
    asm volatile("ldmatrix.sync.aligned.m8n8.x4.shared.b16 {%0,%1,%2,%3},[%4];"
                 : "=r"(r[0]), "=r"(r[1]), "=r"(r[2]), "=r"(r[3]) : "r"(a));
}
__device__ __forceinline__ void ldsm_x2t(unsigned* r, unsigned a) {
    asm volatile("ldmatrix.sync.aligned.m8n8.x2.trans.shared.b16 {%0,%1},[%2];"
                 : "=r"(r[0]), "=r"(r[1]) : "r"(a));
}
__device__ __forceinline__ void ldsm_x4t(unsigned* r, unsigned a) {
    asm volatile("ldmatrix.sync.aligned.m8n8.x4.trans.shared.b16 {%0,%1,%2,%3},[%4];"
                 : "=r"(r[0]), "=r"(r[1]), "=r"(r[2]), "=r"(r[3]) : "r"(a));
}
__device__ __forceinline__ void mma_bf16(float* d, const unsigned* a, const unsigned* b) {
    asm volatile("mma.sync.aligned.m16n8k16.row.col.f32.bf16.bf16.f32 "
                 "{%0,%1,%2,%3},{%4,%5,%6,%7},{%8,%9},{%0,%1,%2,%3};"
                 : "+f"(d[0]), "+f"(d[1]), "+f"(d[2]), "+f"(d[3])
                 : "r"(a[0]), "r"(a[1]), "r"(a[2]), "r"(a[3]),
                   "r"(b[0]), "r"(b[1]));
}
__device__ __forceinline__ void split1(float x, __nv_bfloat16& h, __nv_bfloat16& l) {
    h = __float2bfloat16(x);
    l = __float2bfloat16(x - __bfloat162float(h));
}
__device__ __forceinline__ float ex2(float x) {
    float y; asm("ex2.approx.f32 %0, %1;" : "=f"(y) : "f"(x)); return y;
}
__device__ __forceinline__ void split_pack(float a, float b, unsigned& hi, unsigned& lo) {
    __nv_bfloat16 ah, al, bh, bl;
    split1(a, ah, al); split1(b, bh, bl);
    __nv_bfloat162 th; th.x = ah; th.y = bh;
    __nv_bfloat162 tl; tl.x = al; tl.y = bl;
    hi = *reinterpret_cast<unsigned*>(&th);
    lo = *reinterpret_cast<unsigned*>(&tl);
}

// =====================================================================
// split kernels: fp32 -> (hi, lo) bf16
// =====================================================================
__global__ void split_kernel(const float* __restrict__ src,
                             __nv_bfloat16* __restrict__ hi,
                             __nv_bfloat16* __restrict__ lo, int n)
{
    int i = blockIdx.x * 256 + threadIdx.x;
    if (i < n) { __nv_bfloat16 h, l; split1(src[i], h, l); hi[i] = h; lo[i] = l; }
}

__global__ void split_wqkv_kernel(const float* __restrict__ Wq,
                                  const float* __restrict__ Wk,
                                  const float* __restrict__ Wv)
{
    int i = blockIdx.x * 256 + threadIdx.x;           // over 2048*2560
    const int row = i / NQKV, col = i % NQKV;
    float x;
    if (col < KOFF)       x = Wq[row * (H_*HD_) + col];
    else if (col < VOFF)  x = Wk[row * HD_ + (col - KOFF)];
    else                  x = Wv[row * HD_ + (col - VOFF)];
    __nv_bfloat16 h, l; split1(x, h, l);
    g_Whi[i] = h; g_Wlo[i] = l;
}

// =====================================================================
// bf16x3 tensor-core GEMM (unchanged from R3, proven)
// =====================================================================
#define ASi(buf,hh,r,c) (((((buf)*2 + (hh))*128 + (r))*40) + (c))
#define BSi(buf,hh,r,c) (((((buf)*2 + (hh))*32  + (r))*136) + (c))
#define GEMM_SMEM_BYTES (40960 + 34816)

__device__ __forceinline__ void gemm_load_stage(
    __nv_bfloat16* As, __nv_bfloat16* Bs,
    const __nv_bfloat16* Ahi, const __nv_bfloat16* Alo,
    const __nv_bfloat16* Bhi, const __nv_bfloat16* Blo,
    int N, int K, int brow, int bcol, int tid, int t, int buf)
{
    const int k0 = t * 32;
#pragma unroll
    for (int h = 0; h < 2; ++h) {
        const __nv_bfloat16* Ag = h ? Alo : Ahi;
        const __nv_bfloat16* Bg = h ? Blo : Bhi;
#pragma unroll
        for (int i = 0; i < 2; ++i) {
            const int idx = tid + i * 256;
            const int ra = idx >> 2,  ca = (idx & 3) << 3;
            cpa16(&As[ASi(buf, h, ra, ca)],
                  Ag + (size_t)(brow + ra) * K + k0 + ca);
            const int rb = idx >> 4,  cb = (idx & 15) << 3;
            cpa16(&Bs[BSi(buf, h, rb, cb)],
                  Bg + (size_t)(k0 + rb) * N + bcol + cb);
        }
    }
}

__global__ void __launch_bounds__(256) mma_gemm_kernel(
    const __nv_bfloat16* __restrict__ Ahi, const __nv_bfloat16* __restrict__ Alo,
    const __nv_bfloat16* __restrict__ Bhi, const __nv_bfloat16* __restrict__ Blo,
    float* __restrict__ C, const int N, const int K)
{
    extern __shared__ __align__(16) char smem_raw[];
    __nv_bfloat16* As = (__nv_bfloat16*)(smem_raw);
    __nv_bfloat16* Bs = (__nv_bfloat16*)(smem_raw + 40960);

    const int tid  = threadIdx.x;
    const int brow = blockIdx.y * 128;
    const int bcol = blockIdx.x * 128;
    const int lane = tid & 31;
    const int warp = tid >> 5;
    const int wm   = (warp >> 2) * 64;
    const int wn   = (warp & 3) * 32;

    float acc[4][4][4];
#pragma unroll
    for (int i = 0; i < 4; ++i)
#pragma unroll
        for (int j = 0; j < 4; ++j)
#pragma unroll
            for (int u = 0; u < 4; ++u) acc[i][j][u] = 0.f;

    const int ntiles = K >> 5;
    gemm_load_stage(As, Bs, Ahi, Alo, Bhi, Blo, N, K, brow, bcol, tid, 0, 0);
    CP_COMMIT();

    for (int t = 0; t < ntiles; ++t) {
        if (t + 1 < ntiles) {
            gemm_load_stage(As, Bs, Ahi, Alo, Bhi, Blo, N, K, brow, bcol, tid,
                            t + 1, (t + 1) & 1);
            CP_COMMIT();
            CP_WAIT(1);
        } else {
            CP_WAIT(0);
        }
        __syncthreads();
        const int buf = t & 1;

#pragma unroll
        for (int ks = 0; ks < 32; ks += 16) {
            unsigned bh[4][2], bl[4][2];
#pragma unroll
            for (int nt = 0; nt < 4; ++nt) {
                ldsm_x2t(bh[nt], sptr(&Bs[BSi(buf, 0, ks + (lane & 15), wn + nt*8)]));
                ldsm_x2t(bl[nt], sptr(&Bs[BSi(buf, 1, ks + (lane & 15), wn + nt*8)]));
            }
#pragma unroll
            for (int mt = 0; mt < 4; ++mt) {
                unsigned ah[4], al[4];
                const int ar = wm + mt*16 + (lane & 15);
                const int ac = ks + ((lane >> 4) << 3);
                ldsm_x4(ah, sptr(&As[ASi(buf, 0, ar, ac)]));
                ldsm_x4(al, sptr(&As[ASi(buf, 1, ar, ac)]));
#pragma unroll
                for (int nt = 0; nt < 4; ++nt) {
                    mma_bf16(acc[mt][nt], ah, bh[nt]);
                    mma_bf16(acc[mt][nt], ah, bl[nt]);
                    mma_bf16(acc[mt][nt], al, bh[nt]);
                }
            }
        }
        __syncthreads();
    }

#pragma unroll
    for (int mt = 0; mt < 4; ++mt) {
#pragma unroll
        for (int nt = 0; nt < 4; ++nt) {
            const int r0 = brow + wm + mt*16 + (lane >> 2);
            const int c0 = bcol + wn + nt*8 + ((lane & 3) << 1);
            *(float2*)&C[(size_t)r0 * N + c0]       = make_float2(acc[mt][nt][0], acc[mt][nt][1]);
            *(float2*)&C[(size_t)(r0 + 8) * N + c0] = make_float2(acc[mt][nt][2], acc[mt][nt][3]);
        }
    }
}

// =====================================================================
// RoPE + bf16 hi/lo split of Q (scaled), K (transposed), V.
// grid = 4096 (b*S+s), block = 128 (pair index d)
// =====================================================================
__global__ void rope_split_kernel(const int* __restrict__ pos_ids)
{
    const int bs = blockIdx.x;
    const int d  = threadIdx.x;
    const int b  = bs >> 11;
    const int s  = bs & 2047;
    const int p  = pos_ids[bs];

    const double inv = exp(-((double)d / 128.0) * log(10000.0));
    const double ang = (double)p * inv;
    const float c  = (float)cos(ang);
    const float sn = (float)sin(ang);

    // scale = HD^-0.5 * log2(e), folded into Q for exp2-domain softmax
    const float qsc = 0.0625f * 1.4426950408889634f;

    const float* row = g_qkv + (size_t)bs * NQKV;
#pragma unroll
    for (int h = 0; h < H_; ++h) {
        const float x1 = row[h*HD_ + d], x2 = row[h*HD_ + d + 128];
        const float r1 = (x1*c - x2*sn) * qsc;
        const float r2 = (x2*c + x1*sn) * qsc;
        __nv_bfloat16 hh, ll;
        const size_t o1 = (size_t)bs*D_ + h*HD_ + d;
        split1(r1, hh, ll); g_Qhi[o1] = hh; g_Qlo[o1] = ll;
        split1(r2, hh, ll); g_Qhi[o1+128] = hh; g_Qlo[o1+128] = ll;
    }
    {   // K -> transposed [b][hd][S]
        const float x1 = row[KOFF + d], x2 = row[KOFF + d + 128];
        const float r1 = x1*c - x2*sn;
        const float r2 = x2*c + x1*sn;
        __nv_bfloat16 hh, ll;
        const size_t o1 = (size_t)(b*HD_ + d)*S_ + s;
        const size_t o2 = (size_t)(b*HD_ + d + 128)*S_ + s;
        split1(r1, hh, ll); g_KThi[o1] = hh; g_KTlo[o1] = ll;
        split1(r2, hh, ll); g_KThi[o2] = hh; g_KTlo[o2] = ll;
    }
    {   // V
        const float v1 = row[VOFF + d], v2 = row[VOFF + d + 128];
        __nv_bfloat16 hh, ll;
        const size_t o = (size_t)bs*HD_ + d;
        split1(v1, hh, ll); g_Vhi[o] = hh; g_Vlo[o] = ll;
        split1(v2, hh, ll); g_Vhi[o+128] = hh; g_Vlo[o+128] = ll;
    }
}

// =====================================================================
// Tensor-core flash attention, bf16x3 on S=QK^T and O=PV.
// BM=128 queries, BN=64 keys, 8 warps (warp w owns rows w*16..w*16+15).
// smem: Qhi/Qlo [128][264] resident; K^T chunks [2buf][2][64][72];
//       V half  [2][64][136].
// =====================================================================
#define QS_STR 264
#define KT_STR 72
#define VS_STR 136
#define ATT_Q_ELEMS  (128*QS_STR)
#define ATT_K_ELEMS  (2*2*64*KT_STR)
#define ATT_V_ELEMS  (2*64*VS_STR)
#define ATT2_SMEM_BYTES ((2*ATT_Q_ELEMS + ATT_K_ELEMS + ATT_V_ELEMS) * 2)

__device__ __forceinline__ void att_loadK(__nv_bfloat16* Kb, int tid,
                                          int b, int jt, int kk, int buf)
{
#pragma unroll
    for (int i = 0; i < 4; ++i) {
        const int idx = tid + i*256;
        const int pl = idx >> 9, rem = idx & 511;
        const int r = rem >> 3, c = (rem & 7) << 3;
        const __nv_bfloat16* src = (pl ? g_KTlo : g_KThi)
            + (size_t)(b*HD_ + kk*64 + r)*S_ + jt*64 + c;
        cpa16(&Kb[((buf*2 + pl)*64 + r)*KT_STR + c], src);
    }
}
__device__ __forceinline__ void att_loadV(__nv_bfloat16* Vb, int tid,
                                          int b, int jt, int vh)
{
#pragma unroll
    for (int i = 0; i < 8; ++i) {
        const int idx = tid + i*256;
        const int pl = idx >> 10, rem = idx & 1023;
        const int r = rem >> 4, c = (rem & 15) << 3;
        const __nv_bfloat16* src = (pl ? g_Vlo : g_Vhi)
            + (size_t)(b*S_ + jt*64 + r)*HD_ + vh*128 + c;
        cpa16(&Vb[(pl*64 + r)*VS_STR + c], src);
    }
}

__global__ void __launch_bounds__(256, 1) attn_mma_kernel(const int* __restrict__ amask)
{
    extern __shared__ __align__(16) __nv_bfloat16 smb[];
    __shared__ int am[64];

    __nv_bfloat16* Qh = smb;
    __nv_bfloat16* Ql = smb + ATT_Q_ELEMS;
    __nv_bfloat16* Kb = smb + 2*ATT_Q_ELEMS;
    __nv_bfloat16* Vb = Kb + ATT_K_ELEMS;

    const int tid  = threadIdx.x;
    const int lane = tid & 31;
    const int warp = tid >> 5;

    const int bid = blockIdx.x;                // 256 blocks, largest qt first
    const int qt  = 15 - (bid >> 4);
    const int h   = bid & 7;
    const int b   = (bid >> 3) & 1;
    const int qbase = qt * 128;
    const int jt_max = 2*qt + 1;

    // ---- Q resident load ----
#pragma unroll
    for (int i = 0; i < 32; ++i) {
        const int idx = tid + i*256;
        const int pl = idx >> 12, rem = idx & 4095;
        const int r = rem >> 5, c = (rem & 31) << 3;
        const __nv_bfloat16* src = (pl ? g_Qlo : g_Qhi)
            + (size_t)(b*S_ + qbase + r)*D_ + h*HD_ + c;
        cpa16((pl ? Ql : Qh) + r*QS_STR + c, src);
    }
    CP_COMMIT();
    att_loadK(Kb, tid, b, 0, 0, 0);
    CP_COMMIT();

    float o[32][4];
#pragma unroll
    for (int i = 0; i < 32; ++i)
#pragma unroll
        for (int j = 0; j < 4; ++j) o[i][j] = 0.f;
    float m_lo = -1e30f, m_hi = -1e30f, l_lo = 0.f, l_hi = 0.f;

    const int rl = qbase + warp*16 + (lane >> 2);
    const int rh = rl + 8;

    for (int jt = 0; jt <= jt_max; ++jt) {
        const int kb = jt * 64;
        float s[8][4];
#pragma unroll
        for (int i = 0; i < 8; ++i)
#pragma unroll
            for (int j = 0; j < 4; ++j) s[i][j] = 0.f;

        // ---- S phase: 4 hd-chunks of 64, double-buffered ----
        for (int kk = 0; kk < 4; ++kk) {
            if (kk < 3) {
                att_loadK(Kb, tid, b, jt, kk + 1, (kk + 1) & 1);
                CP_COMMIT();
                CP_WAIT(1);
            } else {
                att_loadV(Vb, tid, b, jt, 0);
                CP_COMMIT();
                if (jt < jt_max) {
                    att_loadK(Kb, tid, b, jt + 1, 0, 0);
                    CP_COMMIT();
                    CP_WAIT(2);
                } else {
                    CP_WAIT(1);
                }
            }
            __syncthreads();
            if (kk == 0 && tid < 64) am[tid] = amask[b*S_ + kb + tid];

            const int buf = kk & 1;
#pragma unroll
            for (int ks = 0; ks < 4; ++ks) {
                unsigned qh_[4], ql_[4];
                const unsigned qaddr_off = (warp*16 + (lane & 15))*QS_STR
                                         + kk*64 + ks*16 + ((lane >> 4) << 3);
                ldsm_x4(qh_, sptr(Qh + qaddr_off));
                ldsm_x4(ql_, sptr(Ql + qaddr_off));
#pragma unroll
                for (int nf2 = 0; nf2 < 4; ++nf2) {
                    unsigned kh_[4], kl_[4];
                    const int koff = (ks*16 + (lane & 15))*KT_STR
                                   + nf2*16 + ((lane >> 4) << 3);
                    ldsm_x4t(kh_, sptr(Kb + (buf*2 + 0)*64*KT_STR + koff));
                    ldsm_x4t(kl_, sptr(Kb + (buf*2 + 1)*64*KT_STR + koff));
                    mma_bf16(s[nf2*2],   qh_, kh_);
                    mma_bf16(s[nf2*2],   ql_, kh_);
                    mma_bf16(s[nf2*2],   qh_, kl_);
                    mma_bf16(s[nf2*2+1], qh_, kh_ + 2);
                    mma_bf16(s[nf2*2+1], ql_, kh_ + 2);
                    mma_bf16(s[nf2*2+1], qh_, kl_ + 2);
                }
            }
            __syncthreads();
        }

        // ---- mask + online softmax (exp2 domain) ----
#pragma unroll
        for (int nf = 0; nf < 8; ++nf) {
#pragma unroll
            for (int j = 0; j < 2; ++j) {
                const int cl = nf*8 + (lane & 3)*2 + j;
                const int cg = kb + cl;
                const bool bad = (am[cl] == 0);
                if (bad || cg > rl) s[nf][j]     = -1e30f;
                if (bad || cg > rh) s[nf][2 + j] = -1e30f;
            }
        }
        float ml = -1e30f, mh = -1e30f;
#pragma unroll
        for (int nf = 0; nf < 8; ++nf) {
            ml = fmaxf(ml, fmaxf(s[nf][0], s[nf][1]));
            mh = fmaxf(mh, fmaxf(s[nf][2], s[nf][3]));
        }
        ml = fmaxf(ml, __shfl_xor_sync(0xffffffffu, ml, 1));
        ml = fmaxf(ml, __shfl_xor_sync(0xffffffffu, ml, 2));
        mh = fmaxf(mh, __shfl_xor_sync(0xffffffffu, mh, 1));
        mh = fmaxf(mh, __shfl_xor_sync(0xffffffffu, mh, 2));

        const float mnl = fmaxf(m_lo, ml);
        const float mnh = fmaxf(m_hi, mh);
        const float al = ex2(m_lo - mnl);
        const float ah = ex2(m_hi - mnh);
        m_lo = mnl; m_hi = mnh;

        float suml = 0.f, sumh = 0.f;
#pragma unroll
        for (int nf = 0; nf < 8; ++nf) {
            s[nf][0] = ex2(s[nf][0] - mnl);  suml += s[nf][0];
            s[nf][1] = ex2(s[nf][1] - mnl);  suml += s[nf][1];
            s[nf][2] = ex2(s[nf][2] - mnh);  sumh += s[nf][2];
            s[nf][3] = ex2(s[nf][3] - mnh);  sumh += s[nf][3];
        }
        suml += __shfl_xor_sync(0xffffffffu, suml, 1);
        suml += __shfl_xor_sync(0xffffffffu, suml, 2);
        sumh += __shfl_xor_sync(0xffffffffu, sumh, 1);
        sumh += __shfl_xor_sync(0xffffffffu, sumh, 2);
        l_lo = l_lo*al + suml;
        l_hi = l_hi*ah + sumh;
#pragma unroll
        for (int nf = 0; nf < 32; ++nf) {
            o[nf][0] *= al; o[nf][1] *= al;
            o[nf][2] *= ah; o[nf][3] *= ah;
        }

        // ---- P accum-frags -> A-frags (bf16 hi/lo), in registers ----
        unsigned pah[4][4], pal[4][4];
#pragma unroll
        for (int kk = 0; kk < 4; ++kk) {
            const int f0 = 2*kk, f1 = 2*kk + 1;
            split_pack(s[f0][0], s[f0][1], pah[kk][0], pal[kk][0]);
            split_pack(s[f0][2], s[f0][3], pah[kk][1], pal[kk][1]);
            split_pack(s[f1][0], s[f1][1], pah[kk][2], pal[kk][2]);
            split_pack(s[f1][2], s[f1][3], pah[kk][3], pal[kk][3]);
        }

        // ---- PV: half 0 ----
        if (jt < jt_max) { CP_WAIT(1); } else { CP_WAIT(0); }
        __syncthreads();
#pragma unroll
        for (int nf2 = 0; nf2 < 8; ++nf2) {
#pragma unroll
            for (int kk = 0; kk < 4; ++kk) {
                unsigned vh_[4], vl_[4];
                const int voff = (kk*16 + (lane & 15))*VS_STR
                               + nf2*16 + ((lane >> 4) << 3);
                ldsm_x4t(vh_, sptr(Vb + voff));
                ldsm_x4t(vl_, sptr(Vb + 64*VS_STR + voff));
                const int o0 = nf2*2;
                mma_bf16(o[o0],   pah[kk], vh_);
                mma_bf16(o[o0],   pal[kk], vh_);
                mma_bf16(o[o0],   pah[kk], vl_);
                mma_bf16(o[o0+1], pah[kk], vh_ + 2);
                mma_bf16(o[o0+1], pal[kk], vh_ + 2);
                mma_bf16(o[o0+1], pah[kk], vl_ + 2);
            }
        }
        __syncthreads();

        // ---- PV: half 1 ----
        att_loadV(Vb, tid, b, jt, 1);
        CP_COMMIT();
        CP_WAIT(0);
        __syncthreads();
#pragma unroll
        for (int nf2 = 0; nf2 < 8; ++nf2) {
#pragma unroll
            for (int kk = 0; kk < 4; ++kk) {
                unsigned vh_[4], vl_[4];
                const int voff = (kk*16 + (lane & 15))*VS_STR
                               + nf2*16 + ((lane >> 4) << 3);
                ldsm_x4t(vh_, sptr(Vb + voff));
                ldsm_x4t(vl_, sptr(Vb + 64*VS_STR + voff));
                const int o0 = 16 + nf2*2;
                mma_bf16(o[o0],   pah[kk], vh_);
                mma_bf16(o[o0],   pal[kk], vh_);
                mma_bf16(o[o0],   pah[kk], vl_);
                mma_bf16(o[o0+1], pah[kk], vh_ + 2);
                mma_bf16(o[o0+1], pal[kk], vh_ + 2);
                mma_bf16(o[o0+1], pah[kk], vl_ + 2);
            }
        }
        __syncthreads();
    }

    // ---- normalize, write O ----
    const float invl = 1.f / l_lo;
    const float invh = 1.f / l_hi;
#pragma unroll
    for (int nf = 0; nf < 32; ++nf) {
        const int c = h*HD_ + nf*8 + (lane & 3)*2;
        *(float2*)&g_ao[(size_t)(b*S_ + rl)*D_ + c] =
            make_float2(o[nf][0]*invl, o[nf][1]*invl);
        *(float2*)&g_ao[(size_t)(b*S_ + rh)*D_ + c] =
            make_float2(o[nf][2]*invh, o[nf][3]*invh);
    }
}

// =====================================================================
extern "C" void kernel_launch(void* const* d_in, const int* in_sizes, int n_in,
                              void* d_out, int out_size)
{
    (void)in_sizes; (void)n_in; (void)out_size;
    const float* X   = (const float*)d_in[0];
    const int*   am  = (const int*)  d_in[1];
    const int*   pos = (const int*)  d_in[2];
    const float* Wq  = (const float*)d_in[3];
    const float* Wk  = (const float*)d_in[4];
    const float* Wv  = (const float*)d_in[5];
    const float* Wo  = (const float*)d_in[6];
    float* out = (float*)d_out;

    cudaFuncSetAttribute(mma_gemm_kernel, cudaFuncAttributeMaxDynamicSharedMemorySize,
                         GEMM_SMEM_BYTES);
    cudaFuncSetAttribute(attn_mma_kernel, cudaFuncAttributeMaxDynamicSharedMemorySize,
                         ATT2_SMEM_BYTES);

    __nv_bfloat16 *Xhi = 0, *Xlo = 0, *Whi = 0, *Wlo = 0;
    __nv_bfloat16 *WOhi = 0, *WOlo = 0, *AOhi = 0, *AOlo = 0;
    float *qkv = 0, *ao = 0;
    cudaGetSymbolAddress((void**)&Xhi,  g_Xhi);
    cudaGetSymbolAddress((void**)&Xlo,  g_Xlo);
    cudaGetSymbolAddress((void**)&Whi,  g_Whi);
    cudaGetSymbolAddress((void**)&Wlo,  g_Wlo);
    cudaGetSymbolAddress((void**)&WOhi, g_WOhi);
    cudaGetSymbolAddress((void**)&WOlo, g_WOlo);
    cudaGetSymbolAddress((void**)&AOhi, g_AOhi);
    cudaGetSymbolAddress((void**)&AOlo, g_AOlo);
    cudaGetSymbolAddress((void**)&qkv,  g_qkv);
    cudaGetSymbolAddress((void**)&ao,   g_ao);

    const int nX  = B_*S_*D_;
    const int nW  = D_*NQKV;
    const int nWO = D_*D_;

    // 1. split inputs to bf16 hi/lo
    split_kernel<<<nX/256, 256>>>(X, Xhi, Xlo, nX);
    split_wqkv_kernel<<<nW/256, 256>>>(Wq, Wk, Wv);
    split_kernel<<<nWO/256, 256>>>(Wo, WOhi, WOlo, nWO);

    // 2. fused QKV projection
    mma_gemm_kernel<<<dim3(NQKV/128, (B_*S_)/128), 256, GEMM_SMEM_BYTES>>>(
        Xhi, Xlo, Whi, Wlo, qkv, NQKV, D_);

    // 3. RoPE + bf16 split of Q (scaled), K^T, V
    rope_split_kernel<<<B_*S_, 128>>>(pos);

    // 4. tensor-core flash attention
    attn_mma_kernel<<<256, 256, ATT2_SMEM_BYTES>>>(am);

    // 5. split attention output, output projection
    split_kernel<<<nX/256, 256>>>(ao, AOhi, AOlo, nX);
    mma_gemm_kernel<<<dim3(D_/128, (B_*S_)/128), 256, GEMM_SMEM_BYTES>>>(
        AOhi, AOlo, WOhi, WOlo, out, D_, D_);
}

// round 7
// speedup vs baseline: 2.5471x; 1.0415x over previous
#include <cuda_runtime.h>
#include <cuda_bf16.h>
#include <stdint.h>
#include <cstdint>
#include <math.h>

#define B_  2
#define S_  2048
#define D_  2048
#define H_  8
#define HD_ 256
#define NQKV 2560          // 2048 Q + 256 K + 256 V
#define KOFF 2048
#define VOFF 2304

// ---- scratch (static device globals; no allocation) ----
__device__ float g_qkv[B_*S_*NQKV];     // [4096, 2560] fp32 (Q|K|V)

__device__ __nv_bfloat16 g_Xhi [B_*S_*D_];
__device__ __nv_bfloat16 g_Xlo [B_*S_*D_];
__device__ __nv_bfloat16 g_Whi [D_*NQKV];     // [k 2048][n 2560]
__device__ __nv_bfloat16 g_Wlo [D_*NQKV];
__device__ __nv_bfloat16 g_WOhi[D_*D_];       // [k][n]
__device__ __nv_bfloat16 g_WOlo[D_*D_];
__device__ __nv_bfloat16 g_AOhi[B_*S_*D_];    // written by attn epilogue
__device__ __nv_bfloat16 g_AOlo[B_*S_*D_];

// attention operands (bf16 hi/lo), written by rope_split
__device__ __nv_bfloat16 g_Qhi [B_*S_*D_];        // [4096][2048], pre-scaled
__device__ __nv_bfloat16 g_Qlo [B_*S_*D_];
__device__ __nv_bfloat16 g_KThi[B_*HD_*S_];       // [b][hd 256][S 2048]  (K^T)
__device__ __nv_bfloat16 g_KTlo[B_*HD_*S_];
__device__ __nv_bfloat16 g_Vhi [B_*S_*HD_];       // [4096][256]
__device__ __nv_bfloat16 g_Vlo [B_*S_*HD_];

// =====================================================================
// helpers
// =====================================================================
__device__ __forceinline__ unsigned sptr(const void* p) {
    return (unsigned)__cvta_generic_to_shared(p);
}
__device__ __forceinline__ void cpa16(void* dst, const void* src) {
    asm volatile("cp.async.cg.shared.global [%0], [%1], 16;\n"
                 :: "r"(sptr(dst)), "l"(src));
}
#define CP_COMMIT() asm volatile("cp.async.commit_group;\n")
#define CP_WAIT(N)  asm volatile("cp.async.wait_group %0;\n" :: "n"(N))

__device__ __forceinline__ void ldsm_x4(unsigned* r, unsigned a) {
    asm volatile("ldmatrix.sync.aligned.m8n8.x4.shared.b16 {%0,%1,%2,%3},[%4];"
                 : "=r"(r[0]), "=r"(r[1]), "=r"(r[2]), "=r"(r[3]) : "r"(a));
}
__device__ __forceinline__ void ldsm_x2t(unsigned* r, unsigned a) {
    asm volatile("ldmatrix.sync.aligned.m8n8.x2.trans.shared.b16 {%0,%1},[%2];"
                 : "=r"(r[0]), "=r"(r[1]) : "r"(a));
}
__device__ __forceinline__ void ldsm_x4t(unsigned* r, unsigned a) {
    asm volatile("ldmatrix.sync.aligned.m8n8.x4.trans.shared.b16 {%0,%1,%2,%3},[%4];"
                 : "=r"(r[0]), "=r"(r[1]), "=r"(r[2]), "=r"(r[3]) : "r"(a));
}
__device__ __forceinline__ void mma_bf16(float* d, const unsigned* a, const unsigned* b) {
    asm volatile("mma.sync.aligned.m16n8k16.row.col.f32.bf16.bf16.f32 "
                 "{%0,%1,%2,%3},{%4,%5,%6,%7},{%8,%9},{%0,%1,%2,%3};"
                 : "+f"(d[0]), "+f"(d[1]), "+f"(d[2]), "+f"(d[3])
                 : "r"(a[0]), "r"(a[1]), "r"(a[2]), "r"(a[3]),
                   "r"(b[0]), "r"(b[1]));
}
__device__ __forceinline__ void split1(float x, __nv_bfloat16& h, __nv_bfloat16& l) {
    h = __float2bfloat16(x);
    l = __float2bfloat16(x - __bfloat162float(h));
}
__device__ __forceinline__ float ex2(float x) {
    float y; asm("ex2.approx.f32 %0, %1;" : "=f"(y) : "f"(x)); return y;
}
__device__ __forceinline__ void split_pack(float a, float b, unsigned& hi, unsigned& lo) {
    __nv_bfloat16 ah, al, bh, bl;
    split1(a, ah, al); split1(b, bh, bl);
    __nv_bfloat162 th; th.x = ah; th.y = bh;
    __nv_bfloat162 tl; tl.x = al; tl.y = bl;
    hi = *reinterpret_cast<unsigned*>(&th);
    lo = *reinterpret_cast<unsigned*>(&tl);
}

// =====================================================================
// split kernels: fp32 -> (hi, lo) bf16
// =====================================================================
__global__ void split_kernel(const float* __restrict__ src,
                             __nv_bfloat16* __restrict__ hi,
                             __nv_bfloat16* __restrict__ lo, int n)
{
    int i = blockIdx.x * 256 + threadIdx.x;
    if (i < n) { __nv_bfloat16 h, l; split1(src[i], h, l); hi[i] = h; lo[i] = l; }
}

__global__ void split_wqkv_kernel(const float* __restrict__ Wq,
                                  const float* __restrict__ Wk,
                                  const float* __restrict__ Wv)
{
    int i = blockIdx.x * 256 + threadIdx.x;           // over 2048*2560
    const int row = i / NQKV, col = i % NQKV;
    float x;
    if (col < KOFF)       x = Wq[row * (H_*HD_) + col];
    else if (col < VOFF)  x = Wk[row * HD_ + (col - KOFF)];
    else                  x = Wv[row * HD_ + (col - VOFF)];
    __nv_bfloat16 h, l; split1(x, h, l);
    g_Whi[i] = h; g_Wlo[i] = l;
}

// =====================================================================
// bf16x3 tensor-core GEMM, templated tile: BM=128 x BN, K-step 32,
// 256 threads = 8 warps in 4(M) x 2(N); warp tile 32 x BN/2.
// =====================================================================
#define ASi(buf,hh,r,c) (((((buf)*2 + (hh))*128 + (r))*40) + (c))

template<int BN, int MINB>
__global__ void __launch_bounds__(256, MINB) tc2_gemm_kernel(
    const __nv_bfloat16* __restrict__ Ahi, const __nv_bfloat16* __restrict__ Alo,
    const __nv_bfloat16* __restrict__ Bhi, const __nv_bfloat16* __restrict__ Blo,
    float* __restrict__ C, const int N, const int K)
{
    constexpr int BSTR = BN + 8;
    constexpr int NT   = BN / 16;            // n-frags per warp
    extern __shared__ __align__(16) char smem_raw[];
    __nv_bfloat16* As = (__nv_bfloat16*)(smem_raw);
    __nv_bfloat16* Bs = (__nv_bfloat16*)(smem_raw + 40960);
    // Bs[buf][plane][32][BSTR]
    #define BSi2(buf,hh,r,c) (((((buf)*2 + (hh))*32 + (r))*BSTR) + (c))

    const int tid  = threadIdx.x;
    const int brow = blockIdx.y * 128;
    const int bcol = blockIdx.x * BN;
    const int lane = tid & 31;
    const int warp = tid >> 5;
    const int wm   = (warp & 3) * 32;
    const int wn   = (warp >> 2) * (BN / 2);

    auto load_stage = [&](int t, int buf) {
        const int k0 = t * 32;
#pragma unroll
        for (int h = 0; h < 2; ++h) {
            const __nv_bfloat16* Ag = h ? Alo : Ahi;
            const __nv_bfloat16* Bg = h ? Blo : Bhi;
#pragma unroll
            for (int i = 0; i < 2; ++i) {      // A: 512 cpa16 per plane
                const int idx = tid + i * 256;
                const int ra = idx >> 2,  ca = (idx & 3) << 3;
                cpa16(&As[ASi(buf, h, ra, ca)],
                      Ag + (size_t)(brow + ra) * K + k0 + ca);
            }
#pragma unroll
            for (int i = 0; i < BN/64; ++i) {  // B: 4*BN cpa16 per plane
                const int idx = tid + i * 256;
                const int rb = idx / (BN/8), cb = (idx % (BN/8)) << 3;
                cpa16(&Bs[BSi2(buf, h, rb, cb)],
                      Bg + (size_t)(k0 + rb) * N + bcol + cb);
            }
        }
    };

    float acc[2][NT][4];
#pragma unroll
    for (int i = 0; i < 2; ++i)
#pragma unroll
        for (int j = 0; j < NT; ++j)
#pragma unroll
            for (int u = 0; u < 4; ++u) acc[i][j][u] = 0.f;

    const int ntiles = K >> 5;
    load_stage(0, 0);
    CP_COMMIT();

    for (int t = 0; t < ntiles; ++t) {
        if (t + 1 < ntiles) {
            load_stage(t + 1, (t + 1) & 1);
            CP_COMMIT();
            CP_WAIT(1);
        } else {
            CP_WAIT(0);
        }
        __syncthreads();
        const int buf = t & 1;

#pragma unroll
        for (int ks = 0; ks < 32; ks += 16) {
            unsigned bh[NT][2], bl[NT][2];
#pragma unroll
            for (int nt = 0; nt < NT; ++nt) {
                ldsm_x2t(bh[nt], sptr(&Bs[BSi2(buf, 0, ks + (lane & 15), wn + nt*8)]));
                ldsm_x2t(bl[nt], sptr(&Bs[BSi2(buf, 1, ks + (lane & 15), wn + nt*8)]));
            }
#pragma unroll
            for (int mt = 0; mt < 2; ++mt) {
                unsigned ah[4], al[4];
                const int ar = wm + mt*16 + (lane & 15);
                const int ac = ks + ((lane >> 4) << 3);
                ldsm_x4(ah, sptr(&As[ASi(buf, 0, ar, ac)]));
                ldsm_x4(al, sptr(&As[ASi(buf, 1, ar, ac)]));
#pragma unroll
                for (int nt = 0; nt < NT; ++nt) {
                    mma_bf16(acc[mt][nt], ah, bh[nt]);
                    mma_bf16(acc[mt][nt], ah, bl[nt]);
                    mma_bf16(acc[mt][nt], al, bh[nt]);
                }
            }
        }
        __syncthreads();
    }

#pragma unroll
    for (int mt = 0; mt < 2; ++mt) {
#pragma unroll
        for (int nt = 0; nt < NT; ++nt) {
            const int r0 = brow + wm + mt*16 + (lane >> 2);
            const int c0 = bcol + wn + nt*8 + ((lane & 3) << 1);
            *(float2*)&C[(size_t)r0 * N + c0]       = make_float2(acc[mt][nt][0], acc[mt][nt][1]);
            *(float2*)&C[(size_t)(r0 + 8) * N + c0] = make_float2(acc[mt][nt][2], acc[mt][nt][3]);
        }
    }
    #undef BSi2
}

#define GEMM64_SMEM  (40960 + 2*2*32*72*2)     // 59392
#define GEMM128_SMEM (40960 + 2*2*32*136*2)    // 75776

// =====================================================================
// RoPE + bf16 hi/lo split of Q (scaled), K (transposed), V.
// =====================================================================
__global__ void rope_split_kernel(const int* __restrict__ pos_ids)
{
    const int bs = blockIdx.x;
    const int d  = threadIdx.x;
    const int b  = bs >> 11;
    const int s  = bs & 2047;
    const int p  = pos_ids[bs];

    const double inv = exp(-((double)d / 128.0) * log(10000.0));
    const double ang = (double)p * inv;
    const float c  = (float)cos(ang);
    const float sn = (float)sin(ang);

    const float qsc = 0.0625f * 1.4426950408889634f;

    const float* row = g_qkv + (size_t)bs * NQKV;
#pragma unroll
    for (int h = 0; h < H_; ++h) {
        const float x1 = row[h*HD_ + d], x2 = row[h*HD_ + d + 128];
        const float r1 = (x1*c - x2*sn) * qsc;
        const float r2 = (x2*c + x1*sn) * qsc;
        __nv_bfloat16 hh, ll;
        const size_t o1 = (size_t)bs*D_ + h*HD_ + d;
        split1(r1, hh, ll); g_Qhi[o1] = hh; g_Qlo[o1] = ll;
        split1(r2, hh, ll); g_Qhi[o1+128] = hh; g_Qlo[o1+128] = ll;
    }
    {
        const float x1 = row[KOFF + d], x2 = row[KOFF + d + 128];
        const float r1 = x1*c - x2*sn;
        const float r2 = x2*c + x1*sn;
        __nv_bfloat16 hh, ll;
        const size_t o1 = (size_t)(b*HD_ + d)*S_ + s;
        const size_t o2 = (size_t)(b*HD_ + d + 128)*S_ + s;
        split1(r1, hh, ll); g_KThi[o1] = hh; g_KTlo[o1] = ll;
        split1(r2, hh, ll); g_KThi[o2] = hh; g_KTlo[o2] = ll;
    }
    {
        const float v1 = row[VOFF + d], v2 = row[VOFF + d + 128];
        __nv_bfloat16 hh, ll;
        const size_t o = (size_t)bs*HD_ + d;
        split1(v1, hh, ll); g_Vhi[o] = hh; g_Vlo[o] = ll;
        split1(v2, hh, ll); g_Vhi[o+128] = hh; g_Vlo[o+128] = ll;
    }
}

// =====================================================================
// Tensor-core flash attention (mma.sync bf16x3) — proven in R4.
// Epilogue writes bf16 hi/lo (AOhi/AOlo) directly for oproj.
// =====================================================================
#define QS_STR 264
#define KT_STR 72
#define VS_STR 136
#define ATT_Q_ELEMS  (128*QS_STR)
#define ATT_K_ELEMS  (2*2*64*KT_STR)
#define ATT_V_ELEMS  (2*64*VS_STR)
#define ATT2_SMEM_BYTES ((2*ATT_Q_ELEMS + ATT_K_ELEMS + ATT_V_ELEMS) * 2)

__device__ __forceinline__ void att_loadK(__nv_bfloat16* Kb, int tid,
                                          int b, int jt, int kk, int buf)
{
#pragma unroll
    for (int i = 0; i < 4; ++i) {
        const int idx = tid + i*256;
        const int pl = idx >> 9, rem = idx & 511;
        const int r = rem >> 3, c = (rem & 7) << 3;
        const __nv_bfloat16* src = (pl ? g_KTlo : g_KThi)
            + (size_t)(b*HD_ + kk*64 + r)*S_ + jt*64 + c;
        cpa16(&Kb[((buf*2 + pl)*64 + r)*KT_STR + c], src);
    }
}
__device__ __forceinline__ void att_loadV(__nv_bfloat16* Vb, int tid,
                                          int b, int jt, int vh)
{
#pragma unroll
    for (int i = 0; i < 8; ++i) {
        const int idx = tid + i*256;
        const int pl = idx >> 10, rem = idx & 1023;
        const int r = rem >> 4, c = (rem & 15) << 3;
        const __nv_bfloat16* src = (pl ? g_Vlo : g_Vhi)
            + (size_t)(b*S_ + jt*64 + r)*HD_ + vh*128 + c;
        cpa16(&Vb[(pl*64 + r)*VS_STR + c], src);
    }
}

__global__ void __launch_bounds__(256, 1) attn_mma_kernel(const int* __restrict__ amask)
{
    extern __shared__ __align__(16) __nv_bfloat16 smb[];
    __shared__ int am[64];

    __nv_bfloat16* Qh = smb;
    __nv_bfloat16* Ql = smb + ATT_Q_ELEMS;
    __nv_bfloat16* Kb = smb + 2*ATT_Q_ELEMS;
    __nv_bfloat16* Vb = Kb + ATT_K_ELEMS;

    const int tid  = threadIdx.x;
    const int lane = tid & 31;
    const int warp = tid >> 5;

    const int bid = blockIdx.x;
    const int qt  = 15 - (bid >> 4);
    const int h   = bid & 7;
    const int b   = (bid >> 3) & 1;
    const int qbase = qt * 128;
    const int jt_max = 2*qt + 1;

#pragma unroll
    for (int i = 0; i < 32; ++i) {
        const int idx = tid + i*256;
        const int pl = idx >> 12, rem = idx & 4095;
        const int r = rem >> 5, c = (rem & 31) << 3;
        const __nv_bfloat16* src = (pl ? g_Qlo : g_Qhi)
            + (size_t)(b*S_ + qbase + r)*D_ + h*HD_ + c;
        cpa16((pl ? Ql : Qh) + r*QS_STR + c, src);
    }
    CP_COMMIT();
    att_loadK(Kb, tid, b, 0, 0, 0);
    CP_COMMIT();

    float o[32][4];
#pragma unroll
    for (int i = 0; i < 32; ++i)
#pragma unroll
        for (int j = 0; j < 4; ++j) o[i][j] = 0.f;
    float m_lo = -1e30f, m_hi = -1e30f, l_lo = 0.f, l_hi = 0.f;

    const int rl = qbase + warp*16 + (lane >> 2);
    const int rh = rl + 8;

    for (int jt = 0; jt <= jt_max; ++jt) {
        const int kb = jt * 64;
        float s[8][4];
#pragma unroll
        for (int i = 0; i < 8; ++i)
#pragma unroll
            for (int j = 0; j < 4; ++j) s[i][j] = 0.f;

        for (int kk = 0; kk < 4; ++kk) {
            if (kk < 3) {
                att_loadK(Kb, tid, b, jt, kk + 1, (kk + 1) & 1);
                CP_COMMIT();
                CP_WAIT(1);
            } else {
                att_loadV(Vb, tid, b, jt, 0);
                CP_COMMIT();
                if (jt < jt_max) {
                    att_loadK(Kb, tid, b, jt + 1, 0, 0);
                    CP_COMMIT();
                    CP_WAIT(2);
                } else {
                    CP_WAIT(1);
                }
            }
            __syncthreads();
            if (kk == 0 && tid < 64) am[tid] = amask[b*S_ + kb + tid];

            const int buf = kk & 1;
#pragma unroll
            for (int ks = 0; ks < 4; ++ks) {
                unsigned qh_[4], ql_[4];
                const unsigned qaddr_off = (warp*16 + (lane & 15))*QS_STR
                                         + kk*64 + ks*16 + ((lane >> 4) << 3);
                ldsm_x4(qh_, sptr(Qh + qaddr_off));
                ldsm_x4(ql_, sptr(Ql + qaddr_off));
#pragma unroll
                for (int nf2 = 0; nf2 < 4; ++nf2) {
                    unsigned kh_[4], kl_[4];
                    const int koff = (ks*16 + (lane & 15))*KT_STR
                                   + nf2*16 + ((lane >> 4) << 3);
                    ldsm_x4t(kh_, sptr(Kb + (buf*2 + 0)*64*KT_STR + koff));
                    ldsm_x4t(kl_, sptr(Kb + (buf*2 + 1)*64*KT_STR + koff));
                    mma_bf16(s[nf2*2],   qh_, kh_);
                    mma_bf16(s[nf2*2],   ql_, kh_);
                    mma_bf16(s[nf2*2],   qh_, kl_);
                    mma_bf16(s[nf2*2+1], qh_, kh_ + 2);
                    mma_bf16(s[nf2*2+1], ql_, kh_ + 2);
                    mma_bf16(s[nf2*2+1], qh_, kl_ + 2);
                }
            }
            __syncthreads();
        }

#pragma unroll
        for (int nf = 0; nf < 8; ++nf) {
#pragma unroll
            for (int j = 0; j < 2; ++j) {
                const int cl = nf*8 + (lane & 3)*2 + j;
                const int cg = kb + cl;
                const bool bad = (am[cl] == 0);
                if (bad || cg > rl) s[nf][j]     = -1e30f;
                if (bad || cg > rh) s[nf][2 + j] = -1e30f;
            }
        }
        float ml = -1e30f, mh = -1e30f;
#pragma unroll
        for (int nf = 0; nf < 8; ++nf) {
            ml = fmaxf(ml, fmaxf(s[nf][0], s[nf][1]));
            mh = fmaxf(mh, fmaxf(s[nf][2], s[nf][3]));
        }
        ml = fmaxf(ml, __shfl_xor_sync(0xffffffffu, ml, 1));
        ml = fmaxf(ml, __shfl_xor_sync(0xffffffffu, ml, 2));
        mh = fmaxf(mh, __shfl_xor_sync(0xffffffffu, mh, 1));
        mh = fmaxf(mh, __shfl_xor_sync(0xffffffffu, mh, 2));

        const float mnl = fmaxf(m_lo, ml);
        const float mnh = fmaxf(m_hi, mh);
        const float al = ex2(m_lo - mnl);
        const float ah = ex2(m_hi - mnh);
        m_lo = mnl; m_hi = mnh;

        float suml = 0.f, sumh = 0.f;
#pragma unroll
        for (int nf = 0; nf < 8; ++nf) {
            s[nf][0] = ex2(s[nf][0] - mnl);  suml += s[nf][0];
            s[nf][1] = ex2(s[nf][1] - mnl);  suml += s[nf][1];
            s[nf][2] = ex2(s[nf][2] - mnh);  sumh += s[nf][2];
            s[nf][3] = ex2(s[nf][3] - mnh);  sumh += s[nf][3];
        }
        suml += __shfl_xor_sync(0xffffffffu, suml, 1);
        suml += __shfl_xor_sync(0xffffffffu, suml, 2);
        sumh += __shfl_xor_sync(0xffffffffu, sumh, 1);
        sumh += __shfl_xor_sync(0xffffffffu, sumh, 2);
        l_lo = l_lo*al + suml;
        l_hi = l_hi*ah + sumh;
#pragma unroll
        for (int nf = 0; nf < 32; ++nf) {
            o[nf][0] *= al; o[nf][1] *= al;
            o[nf][2] *= ah; o[nf][3] *= ah;
        }

        unsigned pah[4][4], pal[4][4];
#pragma unroll
        for (int kk = 0; kk < 4; ++kk) {
            const int f0 = 2*kk, f1 = 2*kk + 1;
            split_pack(s[f0][0], s[f0][1], pah[kk][0], pal[kk][0]);
            split_pack(s[f0][2], s[f0][3], pah[kk][1], pal[kk][1]);
            split_pack(s[f1][0], s[f1][1], pah[kk][2], pal[kk][2]);
            split_pack(s[f1][2], s[f1][3], pah[kk][3], pal[kk][3]);
        }

        if (jt < jt_max) { CP_WAIT(1); } else { CP_WAIT(0); }
        __syncthreads();
#pragma unroll
        for (int nf2 = 0; nf2 < 8; ++nf2) {
#pragma unroll
            for (int kk = 0; kk < 4; ++kk) {
                unsigned vh_[4], vl_[4];
                const int voff = (kk*16 + (lane & 15))*VS_STR
                               + nf2*16 + ((lane >> 4) << 3);
                ldsm_x4t(vh_, sptr(Vb + voff));
                ldsm_x4t(vl_, sptr(Vb + 64*VS_STR + voff));
                const int o0 = nf2*2;
                mma_bf16(o[o0],   pah[kk], vh_);
                mma_bf16(o[o0],   pal[kk], vh_);
                mma_bf16(o[o0],   pah[kk], vl_);
                mma_bf16(o[o0+1], pah[kk], vh_ + 2);
                mma_bf16(o[o0+1], pal[kk], vh_ + 2);
                mma_bf16(o[o0+1], pah[kk], vl_ + 2);
            }
        }
        __syncthreads();

        att_loadV(Vb, tid, b, jt, 1);
        CP_COMMIT();
        CP_WAIT(0);
        __syncthreads();
#pragma unroll
        for (int nf2 = 0; nf2 < 8; ++nf2) {
#pragma unroll
            for (int kk = 0; kk < 4; ++kk) {
                unsigned vh_[4], vl_[4];
                const int voff = (kk*16 + (lane & 15))*VS_STR
                               + nf2*16 + ((lane >> 4) << 3);
                ldsm_x4t(vh_, sptr(Vb + voff));
                ldsm_x4t(vl_, sptr(Vb + 64*VS_STR + voff));
                const int o0 = 16 + nf2*2;
                mma_bf16(o[o0],   pah[kk], vh_);
                mma_bf16(o[o0],   pal[kk], vh_);
                mma_bf16(o[o0],   pah[kk], vl_);
                mma_bf16(o[o0+1], pah[kk], vh_ + 2);
                mma_bf16(o[o0+1], pal[kk], vh_ + 2);
                mma_bf16(o[o0+1], pah[kk], vl_ + 2);
            }
        }
        __syncthreads();
    }

    // ---- normalize, split to bf16 hi/lo, write AO for oproj ----
    const float invl = 1.f / l_lo;
    const float invh = 1.f / l_hi;
#pragma unroll
    for (int nf = 0; nf < 32; ++nf) {
        const int c = h*HD_ + nf*8 + (lane & 3)*2;
        const size_t il = (size_t)(b*S_ + rl)*D_ + c;
        const size_t ih = (size_t)(b*S_ + rh)*D_ + c;
        unsigned hi, lo;
        split_pack(o[nf][0]*invl, o[nf][1]*invl, hi, lo);
        *(unsigned*)&g_AOhi[il] = hi;
        *(unsigned*)&g_AOlo[il] = lo;
        split_pack(o[nf][2]*invh, o[nf][3]*invh, hi, lo);
        *(unsigned*)&g_AOhi[ih] = hi;
        *(unsigned*)&g_AOlo[ih] = lo;
    }
}

// =====================================================================
extern "C" void kernel_launch(void* const* d_in, const int* in_sizes, int n_in,
                              void* d_out, int out_size)
{
    (void)in_sizes; (void)n_in; (void)out_size;
    const float* X   = (const float*)d_in[0];
    const int*   am  = (const int*)  d_in[1];
    const int*   pos = (const int*)  d_in[2];
    const float* Wq  = (const float*)d_in[3];
    const float* Wk  = (const float*)d_in[4];
    const float* Wv  = (const float*)d_in[5];
    const float* Wo  = (const float*)d_in[6];
    float* out = (float*)d_out;

    cudaFuncSetAttribute(tc2_gemm_kernel<64,3>,
                         cudaFuncAttributeMaxDynamicSharedMemorySize, GEMM64_SMEM);
    cudaFuncSetAttribute(tc2_gemm_kernel<128,2>,
                         cudaFuncAttributeMaxDynamicSharedMemorySize, GEMM128_SMEM);
    cudaFuncSetAttribute(attn_mma_kernel,
                         cudaFuncAttributeMaxDynamicSharedMemorySize, ATT2_SMEM_BYTES);

    __nv_bfloat16 *Xhi = 0, *Xlo = 0, *Whi = 0, *Wlo = 0;
    __nv_bfloat16 *WOhi = 0, *WOlo = 0, *AOhi = 0, *AOlo = 0;
    float *qkv = 0;
    cudaGetSymbolAddress((void**)&Xhi,  g_Xhi);
    cudaGetSymbolAddress((void**)&Xlo,  g_Xlo);
    cudaGetSymbolAddress((void**)&Whi,  g_Whi);
    cudaGetSymbolAddress((void**)&Wlo,  g_Wlo);
    cudaGetSymbolAddress((void**)&WOhi, g_WOhi);
    cudaGetSymbolAddress((void**)&WOlo, g_WOlo);
    cudaGetSymbolAddress((void**)&AOhi, g_AOhi);
    cudaGetSymbolAddress((void**)&AOlo, g_AOlo);
    cudaGetSymbolAddress((void**)&qkv,  g_qkv);

    const int nX  = B_*S_*D_;
    const int nW  = D_*NQKV;
    const int nWO = D_*D_;

    // 1. split inputs to bf16 hi/lo
    split_kernel<<<nX/256, 256>>>(X, Xhi, Xlo, nX);
    split_wqkv_kernel<<<nW/256, 256>>>(Wq, Wk, Wv);
    split_kernel<<<nWO/256, 256>>>(Wo, WOhi, WOlo, nWO);

    // 2. fused QKV projection: 128x64 tiles, 3 CTAs/SM, 96% packing
    tc2_gemm_kernel<64,3><<<dim3(NQKV/64, (B_*S_)/128), 256, GEMM64_SMEM>>>(
        Xhi, Xlo, Whi, Wlo, qkv, NQKV, D_);

    // 3. RoPE + bf16 split of Q (scaled), K^T, V
    rope_split_kernel<<<B_*S_, 128>>>(pos);

    // 4. tensor-core flash attention (writes AOhi/AOlo directly)
    attn_mma_kernel<<<256, 256, ATT2_SMEM_BYTES>>>(am);

    // 5. output projection: 128x128 tiles
    tc2_gemm_kernel<128,2><<<dim3(D_/128, (B_*S_)/128), 256, GEMM128_SMEM>>>(
        AOhi, AOlo, WOhi, WOlo, out, D_, D_);
}

// round 8
// speedup vs baseline: 3.4468x; 1.3532x over previous
#include <cuda_runtime.h>
#include <cuda_fp16.h>
#include <stdint.h>
#include <cstdint>
#include <math.h>

#define B_  2
#define S_  2048
#define D_  2048
#define H_  8
#define HD_ 256
#define NQKV 2560          // 2048 Q + 256 K + 256 V
#define KOFF 2048
#define VOFF 2304

// ---- scratch (static device globals; no allocation) ----
__device__ float g_qkv[B_*S_*NQKV];     // [4096, 2560] fp32 (Q|K|V)

__device__ __half g_Xhi [B_*S_*D_];     // A-side: split hi/lo
__device__ __half g_Xlo [B_*S_*D_];
__device__ __half g_Wh  [D_*NQKV];      // B-side: single-rounded
__device__ __half g_WOh [D_*D_];
__device__ __half g_AOhi[B_*S_*D_];     // written by attn epilogue (split)
__device__ __half g_AOlo[B_*S_*D_];

// attention operands, written by rope_split
__device__ __half g_Qhi [B_*S_*D_];     // [4096][2048], pre-scaled, split
__device__ __half g_Qlo [B_*S_*D_];
__device__ __half g_KTh [B_*HD_*S_];    // [b][hd 256][S 2048] (K^T), rounded
__device__ __half g_Vh  [B_*S_*HD_];    // [4096][256], rounded

// =====================================================================
// helpers
// =====================================================================
__device__ __forceinline__ unsigned sptr(const void* p) {
    return (unsigned)__cvta_generic_to_shared(p);
}
__device__ __forceinline__ void cpa16(void* dst, const void* src) {
    asm volatile("cp.async.cg.shared.global [%0], [%1], 16;\n"
                 :: "r"(sptr(dst)), "l"(src));
}
#define CP_COMMIT() asm volatile("cp.async.commit_group;\n")
#define CP_WAIT(N)  asm volatile("cp.async.wait_group %0;\n" :: "n"(N))

__device__ __forceinline__ void ldsm_x4(unsigned* r, unsigned a) {
    asm volatile("ldmatrix.sync.aligned.m8n8.x4.shared.b16 {%0,%1,%2,%3},[%4];"
                 : "=r"(r[0]), "=r"(r[1]), "=r"(r[2]), "=r"(r[3]) : "r"(a));
}
__device__ __forceinline__ void ldsm_x2t(unsigned* r, unsigned a) {
    asm volatile("ldmatrix.sync.aligned.m8n8.x2.trans.shared.b16 {%0,%1},[%2];"
                 : "=r"(r[0]), "=r"(r[1]) : "r"(a));
}
__device__ __forceinline__ void ldsm_x4t(unsigned* r, unsigned a) {
    asm volatile("ldmatrix.sync.aligned.m8n8.x4.trans.shared.b16 {%0,%1,%2,%3},[%4];"
                 : "=r"(r[0]), "=r"(r[1]), "=r"(r[2]), "=r"(r[3]) : "r"(a));
}
__device__ __forceinline__ void mma_f16(float* d, const unsigned* a, const unsigned* b) {
    asm volatile("mma.sync.aligned.m16n8k16.row.col.f32.f16.f16.f32 "
                 "{%0,%1,%2,%3},{%4,%5,%6,%7},{%8,%9},{%0,%1,%2,%3};"
                 : "+f"(d[0]), "+f"(d[1]), "+f"(d[2]), "+f"(d[3])
                 : "r"(a[0]), "r"(a[1]), "r"(a[2]), "r"(a[3]),
                   "r"(b[0]), "r"(b[1]));
}
__device__ __forceinline__ void split1h(float x, __half& h, __half& l) {
    h = __float2half_rn(x);
    l = __float2half_rn(x - __half2float(h));
}
__device__ __forceinline__ float ex2(float x) {
    float y; asm("ex2.approx.f32 %0, %1;" : "=f"(y) : "f"(x)); return y;
}
__device__ __forceinline__ void split_pack_h(float a, float b, unsigned& hi, unsigned& lo) {
    __half ah, al, bh, bl;
    split1h(a, ah, al); split1h(b, bh, bl);
    __half2 th = __halves2half2(ah, bh);
    __half2 tl = __halves2half2(al, bl);
    hi = *reinterpret_cast<unsigned*>(&th);
    lo = *reinterpret_cast<unsigned*>(&tl);
}

// =====================================================================
// prep kernels
// =====================================================================
__global__ void split_kernel(const float* __restrict__ src,
                             __half* __restrict__ hi,
                             __half* __restrict__ lo, int n)
{
    int i = blockIdx.x * 256 + threadIdx.x;
    if (i < n) { __half h, l; split1h(src[i], h, l); hi[i] = h; lo[i] = l; }
}

__global__ void round_wqkv_kernel(const float* __restrict__ Wq,
                                  const float* __restrict__ Wk,
                                  const float* __restrict__ Wv)
{
    int i = blockIdx.x * 256 + threadIdx.x;           // over 2048*2560
    const int row = i / NQKV, col = i % NQKV;
    float x;
    if (col < KOFF)       x = Wq[row * (H_*HD_) + col];
    else if (col < VOFF)  x = Wk[row * HD_ + (col - KOFF)];
    else                  x = Wv[row * HD_ + (col - VOFF)];
    g_Wh[i] = __float2half_rn(x);
}

__global__ void round_kernel(const float* __restrict__ src,
                             __half* __restrict__ dst, int n)
{
    int i = blockIdx.x * 256 + threadIdx.x;
    if (i < n) dst[i] = __float2half_rn(src[i]);
}

// =====================================================================
// fp16x2 tensor-core GEMM: A split (hi/lo), B rounded single.
// BM=128 x BN, K-step 32, 256 threads = 8 warps 4(M) x 2(N).
// =====================================================================
#define ASi(buf,hh,r,c) (((((buf)*2 + (hh))*128 + (r))*40) + (c))

template<int BN, int MINB>
__global__ void __launch_bounds__(256, MINB) tc2_gemm_kernel(
    const __half* __restrict__ Ahi, const __half* __restrict__ Alo,
    const __half* __restrict__ Bh,
    float* __restrict__ C, const int N, const int K)
{
    constexpr int BSTR = BN + 8;
    constexpr int NT   = BN / 16;            // n-frags per warp
    extern __shared__ __align__(16) char smem_raw[];
    __half* As = (__half*)(smem_raw);
    __half* Bs = (__half*)(smem_raw + 40960);
    // Bs[buf][32][BSTR]
    #define BSi2(buf,r,c) ((((buf)*32 + (r))*BSTR) + (c))

    const int tid  = threadIdx.x;
    const int brow = blockIdx.y * 128;
    const int bcol = blockIdx.x * BN;
    const int lane = tid & 31;
    const int warp = tid >> 5;
    const int wm   = (warp & 3) * 32;
    const int wn   = (warp >> 2) * (BN / 2);

    auto load_stage = [&](int t, int buf) {
        const int k0 = t * 32;
#pragma unroll
        for (int h = 0; h < 2; ++h) {          // A planes hi/lo
            const __half* Ag = h ? Alo : Ahi;
#pragma unroll
            for (int i = 0; i < 2; ++i) {
                const int idx = tid + i * 256;
                const int ra = idx >> 2,  ca = (idx & 3) << 3;
                cpa16(&As[ASi(buf, h, ra, ca)],
                      Ag + (size_t)(brow + ra) * K + k0 + ca);
            }
        }
#pragma unroll
        for (int i = 0; i < BN/64; ++i) {      // B single plane
            const int idx = tid + i * 256;
            const int rb = idx / (BN/8), cb = (idx % (BN/8)) << 3;
            cpa16(&Bs[BSi2(buf, rb, cb)],
                  Bh + (size_t)(k0 + rb) * N + bcol + cb);
        }
    };

    float acc[2][NT][4];
#pragma unroll
    for (int i = 0; i < 2; ++i)
#pragma unroll
        for (int j = 0; j < NT; ++j)
#pragma unroll
            for (int u = 0; u < 4; ++u) acc[i][j][u] = 0.f;

    const int ntiles = K >> 5;
    load_stage(0, 0);
    CP_COMMIT();

    for (int t = 0; t < ntiles; ++t) {
        if (t + 1 < ntiles) {
            load_stage(t + 1, (t + 1) & 1);
            CP_COMMIT();
            CP_WAIT(1);
        } else {
            CP_WAIT(0);
        }
        __syncthreads();
        const int buf = t & 1;

#pragma unroll
        for (int ks = 0; ks < 32; ks += 16) {
            unsigned bh[NT][2];
#pragma unroll
            for (int nt = 0; nt < NT; ++nt)
                ldsm_x2t(bh[nt], sptr(&Bs[BSi2(buf, ks + (lane & 15), wn + nt*8)]));
#pragma unroll
            for (int mt = 0; mt < 2; ++mt) {
                unsigned ah[4], al[4];
                const int ar = wm + mt*16 + (lane & 15);
                const int ac = ks + ((lane >> 4) << 3);
                ldsm_x4(ah, sptr(&As[ASi(buf, 0, ar, ac)]));
                ldsm_x4(al, sptr(&As[ASi(buf, 1, ar, ac)]));
#pragma unroll
                for (int nt = 0; nt < NT; ++nt) {
                    mma_f16(acc[mt][nt], ah, bh[nt]);
                    mma_f16(acc[mt][nt], al, bh[nt]);
                }
            }
        }
        __syncthreads();
    }

#pragma unroll
    for (int mt = 0; mt < 2; ++mt) {
#pragma unroll
        for (int nt = 0; nt < NT; ++nt) {
            const int r0 = brow + wm + mt*16 + (lane >> 2);
            const int c0 = bcol + wn + nt*8 + ((lane & 3) << 1);
            *(float2*)&C[(size_t)r0 * N + c0]       = make_float2(acc[mt][nt][0], acc[mt][nt][1]);
            *(float2*)&C[(size_t)(r0 + 8) * N + c0] = make_float2(acc[mt][nt][2], acc[mt][nt][3]);
        }
    }
    #undef BSi2
}

#define GEMM64_SMEM  (40960 + 2*32*72*2)      // 50176
#define GEMM128_SMEM (40960 + 2*32*136*2)     // 58368

// =====================================================================
// RoPE + fp16 prep: Q split (scaled), K^T rounded, V rounded.
// =====================================================================
__global__ void rope_split_kernel(const int* __restrict__ pos_ids)
{
    const int bs = blockIdx.x;
    const int d  = threadIdx.x;
    const int b  = bs >> 11;
    const int s  = bs & 2047;
    const int p  = pos_ids[bs];

    const double inv = exp(-((double)d / 128.0) * log(10000.0));
    const double ang = (double)p * inv;
    const float c  = (float)cos(ang);
    const float sn = (float)sin(ang);

    const float qsc = 0.0625f * 1.4426950408889634f;

    const float* row = g_qkv + (size_t)bs * NQKV;
#pragma unroll
    for (int h = 0; h < H_; ++h) {
        const float x1 = row[h*HD_ + d], x2 = row[h*HD_ + d + 128];
        const float r1 = (x1*c - x2*sn) * qsc;
        const float r2 = (x2*c + x1*sn) * qsc;
        __half hh, ll;
        const size_t o1 = (size_t)bs*D_ + h*HD_ + d;
        split1h(r1, hh, ll); g_Qhi[o1] = hh; g_Qlo[o1] = ll;
        split1h(r2, hh, ll); g_Qhi[o1+128] = hh; g_Qlo[o1+128] = ll;
    }
    {
        const float x1 = row[KOFF + d], x2 = row[KOFF + d + 128];
        g_KTh[(size_t)(b*HD_ + d)*S_ + s]       = __float2half_rn(x1*c - x2*sn);
        g_KTh[(size_t)(b*HD_ + d + 128)*S_ + s] = __float2half_rn(x2*c + x1*sn);
    }
    {
        const size_t o = (size_t)bs*HD_ + d;
        g_Vh[o]       = __float2half_rn(row[VOFF + d]);
        g_Vh[o + 128] = __float2half_rn(row[VOFF + d + 128]);
    }
}

// =====================================================================
// Tensor-core flash attention, fp16x2.
// BM=128 q, BN=64 k, 8 warps. Q split resident; K/V single plane.
// =====================================================================
#define QS_STR 264
#define KT_STR 72
#define VS_STR 136
#define ATT_Q_ELEMS  (128*QS_STR)
#define ATT_K_ELEMS  (2*64*KT_STR)     // 2 buffers, single plane
#define ATT_V_ELEMS  (64*VS_STR)       // single plane
#define ATT2_SMEM_BYTES ((2*ATT_Q_ELEMS + ATT_K_ELEMS + ATT_V_ELEMS) * 2)

__device__ __forceinline__ void att_loadK(__half* Kb, int tid,
                                          int b, int jt, int kk, int buf)
{
#pragma unroll
    for (int i = 0; i < 2; ++i) {
        const int idx = tid + i*256;
        const int r = idx >> 3, c = (idx & 7) << 3;
        cpa16(&Kb[(buf*64 + r)*KT_STR + c],
              g_KTh + (size_t)(b*HD_ + kk*64 + r)*S_ + jt*64 + c);
    }
}
__device__ __forceinline__ void att_loadV(__half* Vb, int tid,
                                          int b, int jt, int vh)
{
#pragma unroll
    for (int i = 0; i < 4; ++i) {
        const int idx = tid + i*256;
        const int r = idx >> 4, c = (idx & 15) << 3;
        cpa16(&Vb[r*VS_STR + c],
              g_Vh + (size_t)(b*S_ + jt*64 + r)*HD_ + vh*128 + c);
    }
}

__global__ void __launch_bounds__(256, 1) attn_mma_kernel(const int* __restrict__ amask)
{
    extern __shared__ __align__(16) __half smb[];
    __shared__ int am[64];

    __half* Qh = smb;
    __half* Ql = smb + ATT_Q_ELEMS;
    __half* Kb = smb + 2*ATT_Q_ELEMS;
    __half* Vb = Kb + ATT_K_ELEMS;

    const int tid  = threadIdx.x;
    const int lane = tid & 31;
    const int warp = tid >> 5;

    const int bid = blockIdx.x;
    const int qt  = 15 - (bid >> 4);
    const int h   = bid & 7;
    const int b   = (bid >> 3) & 1;
    const int qbase = qt * 128;
    const int jt_max = 2*qt + 1;

#pragma unroll
    for (int i = 0; i < 32; ++i) {
        const int idx = tid + i*256;
        const int pl = idx >> 12, rem = idx & 4095;
        const int r = rem >> 5, c = (rem & 31) << 3;
        const __half* src = (pl ? g_Qlo : g_Qhi)
            + (size_t)(b*S_ + qbase + r)*D_ + h*HD_ + c;
        cpa16((pl ? Ql : Qh) + r*QS_STR + c, src);
    }
    CP_COMMIT();
    att_loadK(Kb, tid, b, 0, 0, 0);
    CP_COMMIT();

    float o[32][4];
#pragma unroll
    for (int i = 0; i < 32; ++i)
#pragma unroll
        for (int j = 0; j < 4; ++j) o[i][j] = 0.f;
    float m_lo = -1e30f, m_hi = -1e30f, l_lo = 0.f, l_hi = 0.f;

    const int rl = qbase + warp*16 + (lane >> 2);
    const int rh = rl + 8;

    for (int jt = 0; jt <= jt_max; ++jt) {
        const int kb = jt * 64;
        float s[8][4];
#pragma unroll
        for (int i = 0; i < 8; ++i)
#pragma unroll
            for (int j = 0; j < 4; ++j) s[i][j] = 0.f;

        for (int kk = 0; kk < 4; ++kk) {
            if (kk < 3) {
                att_loadK(Kb, tid, b, jt, kk + 1, (kk + 1) & 1);
                CP_COMMIT();
                CP_WAIT(1);
            } else {
                att_loadV(Vb, tid, b, jt, 0);
                CP_COMMIT();
                if (jt < jt_max) {
                    att_loadK(Kb, tid, b, jt + 1, 0, 0);
                    CP_COMMIT();
                    CP_WAIT(2);
                } else {
                    CP_WAIT(1);
                }
            }
            __syncthreads();
            if (kk == 0 && tid < 64) am[tid] = amask[b*S_ + kb + tid];

            const int buf = kk & 1;
#pragma unroll
            for (int ks = 0; ks < 4; ++ks) {
                unsigned qh_[4], ql_[4];
                const unsigned qaddr_off = (warp*16 + (lane & 15))*QS_STR
                                         + kk*64 + ks*16 + ((lane >> 4) << 3);
                ldsm_x4(qh_, sptr(Qh + qaddr_off));
                ldsm_x4(ql_, sptr(Ql + qaddr_off));
#pragma unroll
                for (int nf2 = 0; nf2 < 4; ++nf2) {
                    unsigned kh_[4];
                    const int koff = (ks*16 + (lane & 15))*KT_STR
                                   + nf2*16 + ((lane >> 4) << 3);
                    ldsm_x4t(kh_, sptr(Kb + buf*64*KT_STR + koff));
                    mma_f16(s[nf2*2],   qh_, kh_);
                    mma_f16(s[nf2*2],   ql_, kh_);
                    mma_f16(s[nf2*2+1], qh_, kh_ + 2);
                    mma_f16(s[nf2*2+1], ql_, kh_ + 2);
                }
            }
            __syncthreads();
        }

#pragma unroll
        for (int nf = 0; nf < 8; ++nf) {
#pragma unroll
            for (int j = 0; j < 2; ++j) {
                const int cl = nf*8 + (lane & 3)*2 + j;
                const int cg = kb + cl;
                const bool bad = (am[cl] == 0);
                if (bad || cg > rl) s[nf][j]     = -1e30f;
                if (bad || cg > rh) s[nf][2 + j] = -1e30f;
            }
        }
        float ml = -1e30f, mh = -1e30f;
#pragma unroll
        for (int nf = 0; nf < 8; ++nf) {
            ml = fmaxf(ml, fmaxf(s[nf][0], s[nf][1]));
            mh = fmaxf(mh, fmaxf(s[nf][2], s[nf][3]));
        }
        ml = fmaxf(ml, __shfl_xor_sync(0xffffffffu, ml, 1));
        ml = fmaxf(ml, __shfl_xor_sync(0xffffffffu, ml, 2));
        mh = fmaxf(mh, __shfl_xor_sync(0xffffffffu, mh, 1));
        mh = fmaxf(mh, __shfl_xor_sync(0xffffffffu, mh, 2));

        const float mnl = fmaxf(m_lo, ml);
        const float mnh = fmaxf(m_hi, mh);
        const float al = ex2(m_lo - mnl);
        const float ah = ex2(m_hi - mnh);
        m_lo = mnl; m_hi = mnh;

        float suml = 0.f, sumh = 0.f;
#pragma unroll
        for (int nf = 0; nf < 8; ++nf) {
            s[nf][0] = ex2(s[nf][0] - mnl);  suml += s[nf][0];
            s[nf][1] = ex2(s[nf][1] - mnl);  suml += s[nf][1];
            s[nf][2] = ex2(s[nf][2] - mnh);  sumh += s[nf][2];
            s[nf][3] = ex2(s[nf][3] - mnh);  sumh += s[nf][3];
        }
        suml += __shfl_xor_sync(0xffffffffu, suml, 1);
        suml += __shfl_xor_sync(0xffffffffu, suml, 2);
        sumh += __shfl_xor_sync(0xffffffffu, sumh, 1);
        sumh += __shfl_xor_sync(0xffffffffu, sumh, 2);
        l_lo = l_lo*al + suml;
        l_hi = l_hi*ah + sumh;
#pragma unroll
        for (int nf = 0; nf < 32; ++nf) {
            o[nf][0] *= al; o[nf][1] *= al;
            o[nf][2] *= ah; o[nf][3] *= ah;
        }

        // P accum-frags -> fp16 A-frags (hi/lo), in registers
        unsigned pah[4][4], pal[4][4];
#pragma unroll
        for (int kk = 0; kk < 4; ++kk) {
            const int f0 = 2*kk, f1 = 2*kk + 1;
            split_pack_h(s[f0][0], s[f0][1], pah[kk][0], pal[kk][0]);
            split_pack_h(s[f0][2], s[f0][3], pah[kk][1], pal[kk][1]);
            split_pack_h(s[f1][0], s[f1][1], pah[kk][2], pal[kk][2]);
            split_pack_h(s[f1][2], s[f1][3], pah[kk][3], pal[kk][3]);
        }

        // ---- PV: half 0 ----
        if (jt < jt_max) { CP_WAIT(1); } else { CP_WAIT(0); }
        __syncthreads();
#pragma unroll
        for (int nf2 = 0; nf2 < 8; ++nf2) {
#pragma unroll
            for (int kk = 0; kk < 4; ++kk) {
                unsigned vh_[4];
                const int voff = (kk*16 + (lane & 15))*VS_STR
                               + nf2*16 + ((lane >> 4) << 3);
                ldsm_x4t(vh_, sptr(Vb + voff));
                const int o0 = nf2*2;
                mma_f16(o[o0],   pah[kk], vh_);
                mma_f16(o[o0],   pal[kk], vh_);
                mma_f16(o[o0+1], pah[kk], vh_ + 2);
                mma_f16(o[o0+1], pal[kk], vh_ + 2);
            }
        }
        __syncthreads();

        // ---- PV: half 1 ----
        att_loadV(Vb, tid, b, jt, 1);
        CP_COMMIT();
        CP_WAIT(0);
        __syncthreads();
#pragma unroll
        for (int nf2 = 0; nf2 < 8; ++nf2) {
#pragma unroll
            for (int kk = 0; kk < 4; ++kk) {
                unsigned vh_[4];
                const int voff = (kk*16 + (lane & 15))*VS_STR
                               + nf2*16 + ((lane >> 4) << 3);
                ldsm_x4t(vh_, sptr(Vb + voff));
                const int o0 = 16 + nf2*2;
                mma_f16(o[o0],   pah[kk], vh_);
                mma_f16(o[o0],   pal[kk], vh_);
                mma_f16(o[o0+1], pah[kk], vh_ + 2);
                mma_f16(o[o0+1], pal[kk], vh_ + 2);
            }
        }
        __syncthreads();
    }

    // ---- normalize, split to fp16 hi/lo, write AO for oproj ----
    const float invl = 1.f / l_lo;
    const float invh = 1.f / l_hi;
#pragma unroll
    for (int nf = 0; nf < 32; ++nf) {
        const int c = h*HD_ + nf*8 + (lane & 3)*2;
        const size_t il = (size_t)(b*S_ + rl)*D_ + c;
        const size_t ih = (size_t)(b*S_ + rh)*D_ + c;
        unsigned hi, lo;
        split_pack_h(o[nf][0]*invl, o[nf][1]*invl, hi, lo);
        *(unsigned*)&g_AOhi[il] = hi;
        *(unsigned*)&g_AOlo[il] = lo;
        split_pack_h(o[nf][2]*invh, o[nf][3]*invh, hi, lo);
        *(unsigned*)&g_AOhi[ih] = hi;
        *(unsigned*)&g_AOlo[ih] = lo;
    }
}

// =====================================================================
extern "C" void kernel_launch(void* const* d_in, const int* in_sizes, int n_in,
                              void* d_out, int out_size)
{
    (void)in_sizes; (void)n_in; (void)out_size;
    const float* X   = (const float*)d_in[0];
    const int*   am  = (const int*)  d_in[1];
    const int*   pos = (const int*)  d_in[2];
    const float* Wq  = (const float*)d_in[3];
    const float* Wk  = (const float*)d_in[4];
    const float* Wv  = (const float*)d_in[5];
    const float* Wo  = (const float*)d_in[6];
    float* out = (float*)d_out;

    cudaFuncSetAttribute(tc2_gemm_kernel<64,3>,
                         cudaFuncAttributeMaxDynamicSharedMemorySize, GEMM64_SMEM);
    cudaFuncSetAttribute(tc2_gemm_kernel<128,2>,
                         cudaFuncAttributeMaxDynamicSharedMemorySize, GEMM128_SMEM);
    cudaFuncSetAttribute(attn_mma_kernel,
                         cudaFuncAttributeMaxDynamicSharedMemorySize, ATT2_SMEM_BYTES);

    __half *Xhi = 0, *Xlo = 0, *Wh = 0, *WOh = 0, *AOhi = 0, *AOlo = 0;
    float *qkv = 0;
    cudaGetSymbolAddress((void**)&Xhi,  g_Xhi);
    cudaGetSymbolAddress((void**)&Xlo,  g_Xlo);
    cudaGetSymbolAddress((void**)&Wh,   g_Wh);
    cudaGetSymbolAddress((void**)&WOh,  g_WOh);
    cudaGetSymbolAddress((void**)&AOhi, g_AOhi);
    cudaGetSymbolAddress((void**)&AOlo, g_AOlo);
    cudaGetSymbolAddress((void**)&qkv,  g_qkv);

    const int nX  = B_*S_*D_;
    const int nW  = D_*NQKV;
    const int nWO = D_*D_;

    // 1. prep inputs: X split fp16 hi/lo; W, Wo rounded fp16
    split_kernel<<<nX/256, 256>>>(X, Xhi, Xlo, nX);
    round_wqkv_kernel<<<nW/256, 256>>>(Wq, Wk, Wv);
    round_kernel<<<nWO/256, 256>>>(Wo, WOh, nWO);

    // 2. fused QKV projection (fp16x2): 128x64 tiles
    tc2_gemm_kernel<64,3><<<dim3(NQKV/64, (B_*S_)/128), 256, GEMM64_SMEM>>>(
        Xhi, Xlo, Wh, qkv, NQKV, D_);

    // 3. RoPE + fp16 prep of Q (split, scaled), K^T, V
    rope_split_kernel<<<B_*S_, 128>>>(pos);

    // 4. tensor-core flash attention (fp16x2, writes AOhi/AOlo)
    attn_mma_kernel<<<256, 256, ATT2_SMEM_BYTES>>>(am);

    // 5. output projection (fp16x2): 128x128 tiles
    tc2_gemm_kernel<128,2><<<dim3(D_/128, (B_*S_)/128), 256, GEMM128_SMEM>>>(
        AOhi, AOlo, WOh, out, D_, D_);
}

// round 9
// speedup vs baseline: 3.4956x; 1.0142x over previous
#include <cuda_runtime.h>
#include <cuda_fp16.h>
#include <stdint.h>
#include <cstdint>
#include <math.h>

#define B_  2
#define S_  2048
#define D_  2048
#define H_  8
#define HD_ 256
#define NQKV 2560          // 2048 Q + 256 K + 256 V
#define KOFF 2048
#define VOFF 2304

// ---- scratch (static device globals; no allocation) ----
__device__ float g_qkv[B_*S_*NQKV];     // [4096, 2560] fp32 (Q|K|V)

__device__ __half g_Xhi [B_*S_*D_];     // A-side: split hi/lo
__device__ __half g_Xlo [B_*S_*D_];
__device__ __half g_Wh  [D_*NQKV];      // B-side: single-rounded
__device__ __half g_WOh [D_*D_];
__device__ __half g_AOhi[B_*S_*D_];     // written by attn epilogue (split)
__device__ __half g_AOlo[B_*S_*D_];

// attention operands, written by rope_split
__device__ __half g_Qhi [B_*S_*D_];     // [4096][2048], pre-scaled, split
__device__ __half g_Qlo [B_*S_*D_];
__device__ __half g_KTh [B_*HD_*S_];    // [b][hd 256][S 2048] (K^T), rounded
__device__ __half g_Vh  [B_*S_*HD_];    // [4096][256], rounded

// =====================================================================
// helpers
// =====================================================================
__device__ __forceinline__ unsigned sptr(const void* p) {
    return (unsigned)__cvta_generic_to_shared(p);
}
__device__ __forceinline__ void cpa16(void* dst, const void* src) {
    asm volatile("cp.async.cg.shared.global [%0], [%1], 16;\n"
                 :: "r"(sptr(dst)), "l"(src));
}
#define CP_COMMIT() asm volatile("cp.async.commit_group;\n")
#define CP_WAIT(N)  asm volatile("cp.async.wait_group %0;\n" :: "n"(N))

__device__ __forceinline__ void ldsm_x4(unsigned* r, unsigned a) {
    asm volatile("ldmatrix.sync.aligned.m8n8.x4.shared.b16 {%0,%1,%2,%3},[%4];"
                 : "=r"(r[0]), "=r"(r[1]), "=r"(r[2]), "=r"(r[3]) : "r"(a));
}
__device__ __forceinline__ void ldsm_x4t(unsigned* r, unsigned a) {
    asm volatile("ldmatrix.sync.aligned.m8n8.x4.trans.shared.b16 {%0,%1,%2,%3},[%4];"
                 : "=r"(r[0]), "=r"(r[1]), "=r"(r[2]), "=r"(r[3]) : "r"(a));
}
__device__ __forceinline__ void mma_f16(float* d, const unsigned* a, const unsigned* b) {
    asm volatile("mma.sync.aligned.m16n8k16.row.col.f32.f16.f16.f32 "
                 "{%0,%1,%2,%3},{%4,%5,%6,%7},{%8,%9},{%0,%1,%2,%3};"
                 : "+f"(d[0]), "+f"(d[1]), "+f"(d[2]), "+f"(d[3])
                 : "r"(a[0]), "r"(a[1]), "r"(a[2]), "r"(a[3]),
                   "r"(b[0]), "r"(b[1]));
}
__device__ __forceinline__ void split1h(float x, __half& h, __half& l) {
    h = __float2half_rn(x);
    l = __float2half_rn(x - __half2float(h));
}
__device__ __forceinline__ float ex2(float x) {
    float y; asm("ex2.approx.f32 %0, %1;" : "=f"(y) : "f"(x)); return y;
}
__device__ __forceinline__ void split_pack_h(float a, float b, unsigned& hi, unsigned& lo) {
    __half ah, al, bh, bl;
    split1h(a, ah, al); split1h(b, bh, bl);
    __half2 th = __halves2half2(ah, bh);
    __half2 tl = __halves2half2(al, bl);
    hi = *reinterpret_cast<unsigned*>(&th);
    lo = *reinterpret_cast<unsigned*>(&tl);
}

// =====================================================================
// merged prep: X split; Wqkv round; Wo round — one launch
// =====================================================================
#define NX_  (B_*S_*D_)
#define NW_  (D_*NQKV)
#define NWO_ (D_*D_)

__global__ void prep_kernel(const float* __restrict__ X,
                            const float* __restrict__ Wq,
                            const float* __restrict__ Wk,
                            const float* __restrict__ Wv,
                            const float* __restrict__ Wo)
{
    int i = blockIdx.x * 256 + threadIdx.x;
    if (i < NX_) {
        __half h, l; split1h(X[i], h, l);
        g_Xhi[i] = h; g_Xlo[i] = l;
    } else if (i < NX_ + NW_) {
        const int j = i - NX_;
        const int row = j / NQKV, col = j % NQKV;
        float x;
        if (col < KOFF)       x = Wq[row * (H_*HD_) + col];
        else if (col < VOFF)  x = Wk[row * HD_ + (col - KOFF)];
        else                  x = Wv[row * HD_ + (col - VOFF)];
        g_Wh[j] = __float2half_rn(x);
    } else {
        const int j = i - NX_ - NW_;
        g_WOh[j] = __float2half_rn(Wo[j]);
    }
}

// =====================================================================
// fp16x2 tensor-core GEMM: A split (hi/lo), B rounded single.
// BM=128 x BN=128, K-step 32, 256 threads = 8 warps 4(M) x 2(N);
// warp tile 32x64; B frags via ldsm_x4t (16-col). mma:ldsm = 4:1.
// =====================================================================
#define ASi(buf,hh,r,c) (((((buf)*2 + (hh))*128 + (r))*40) + (c))
#define BSTR3 136
#define BSi3(buf,r,c) ((((buf)*32 + (r))*BSTR3) + (c))
#define GEMM3_SMEM (40960 + 2*32*BSTR3*2)     // 58368

__global__ void __launch_bounds__(256, 2) tc3_gemm_kernel(
    const __half* __restrict__ Ahi, const __half* __restrict__ Alo,
    const __half* __restrict__ Bh,
    float* __restrict__ C, const int N, const int K)
{
    extern __shared__ __align__(16) char smem_raw[];
    __half* As = (__half*)(smem_raw);
    __half* Bs = (__half*)(smem_raw + 40960);

    const int tid  = threadIdx.x;
    const int brow = blockIdx.y * 128;
    const int bcol = blockIdx.x * 128;
    const int lane = tid & 31;
    const int warp = tid >> 5;
    const int wm   = (warp & 3) * 32;
    const int wn   = (warp >> 2) * 64;

    auto load_stage = [&](int t, int buf) {
        const int k0 = t * 32;
#pragma unroll
        for (int h = 0; h < 2; ++h) {          // A planes hi/lo
            const __half* Ag = h ? Alo : Ahi;
#pragma unroll
            for (int i = 0; i < 2; ++i) {
                const int idx = tid + i * 256;
                const int ra = idx >> 2,  ca = (idx & 3) << 3;
                cpa16(&As[ASi(buf, h, ra, ca)],
                      Ag + (size_t)(brow + ra) * K + k0 + ca);
            }
        }
#pragma unroll
        for (int i = 0; i < 2; ++i) {          // B single plane: 32x128
            const int idx = tid + i * 256;
            const int rb = idx >> 4, cb = (idx & 15) << 3;
            cpa16(&Bs[BSi3(buf, rb, cb)],
                  Bh + (size_t)(k0 + rb) * N + bcol + cb);
        }
    };

    float acc[2][8][4];
#pragma unroll
    for (int i = 0; i < 2; ++i)
#pragma unroll
        for (int j = 0; j < 8; ++j)
#pragma unroll
            for (int u = 0; u < 4; ++u) acc[i][j][u] = 0.f;

    const int ntiles = K >> 5;
    load_stage(0, 0);
    CP_COMMIT();

    for (int t = 0; t < ntiles; ++t) {
        if (t + 1 < ntiles) {
            load_stage(t + 1, (t + 1) & 1);
            CP_COMMIT();
            CP_WAIT(1);
        } else {
            CP_WAIT(0);
        }
        __syncthreads();
        const int buf = t & 1;

#pragma unroll
        for (int ks = 0; ks < 32; ks += 16) {
            unsigned bf[4][4];
#pragma unroll
            for (int nt2 = 0; nt2 < 4; ++nt2)
                ldsm_x4t(bf[nt2], sptr(&Bs[BSi3(buf, ks + (lane & 15),
                                        wn + nt2*16 + ((lane >> 4) << 3))]));
#pragma unroll
            for (int mt = 0; mt < 2; ++mt) {
                unsigned ah[4], al[4];
                const int ar = wm + mt*16 + (lane & 15);
                const int ac = ks + ((lane >> 4) << 3);
                ldsm_x4(ah, sptr(&As[ASi(buf, 0, ar, ac)]));
                ldsm_x4(al, sptr(&As[ASi(buf, 1, ar, ac)]));
#pragma unroll
                for (int nt2 = 0; nt2 < 4; ++nt2) {
                    mma_f16(acc[mt][2*nt2],   ah, bf[nt2]);
                    mma_f16(acc[mt][2*nt2],   al, bf[nt2]);
                    mma_f16(acc[mt][2*nt2+1], ah, bf[nt2] + 2);
                    mma_f16(acc[mt][2*nt2+1], al, bf[nt2] + 2);
                }
            }
        }
        __syncthreads();
    }

#pragma unroll
    for (int mt = 0; mt < 2; ++mt) {
#pragma unroll
        for (int nt = 0; nt < 8; ++nt) {
            const int r0 = brow + wm + mt*16 + (lane >> 2);
            const int c0 = bcol + wn + nt*8 + ((lane & 3) << 1);
            *(float2*)&C[(size_t)r0 * N + c0]       = make_float2(acc[mt][nt][0], acc[mt][nt][1]);
            *(float2*)&C[(size_t)(r0 + 8) * N + c0] = make_float2(acc[mt][nt][2], acc[mt][nt][3]);
        }
    }
}

// =====================================================================
// RoPE + fp16 prep: Q split (scaled), K^T rounded, V rounded.
// =====================================================================
__global__ void rope_split_kernel(const int* __restrict__ pos_ids)
{
    const int bs = blockIdx.x;
    const int d  = threadIdx.x;
    const int b  = bs >> 11;
    const int s  = bs & 2047;
    const int p  = pos_ids[bs];

    const double inv = exp(-((double)d / 128.0) * log(10000.0));
    const double ang = (double)p * inv;
    const float c  = (float)cos(ang);
    const float sn = (float)sin(ang);

    const float qsc = 0.0625f * 1.4426950408889634f;

    const float* row = g_qkv + (size_t)bs * NQKV;
#pragma unroll
    for (int h = 0; h < H_; ++h) {
        const float x1 = row[h*HD_ + d], x2 = row[h*HD_ + d + 128];
        const float r1 = (x1*c - x2*sn) * qsc;
        const float r2 = (x2*c + x1*sn) * qsc;
        __half hh, ll;
        const size_t o1 = (size_t)bs*D_ + h*HD_ + d;
        split1h(r1, hh, ll); g_Qhi[o1] = hh; g_Qlo[o1] = ll;
        split1h(r2, hh, ll); g_Qhi[o1+128] = hh; g_Qlo[o1+128] = ll;
    }
    {
        const float x1 = row[KOFF + d], x2 = row[KOFF + d + 128];
        g_KTh[(size_t)(b*HD_ + d)*S_ + s]       = __float2half_rn(x1*c - x2*sn);
        g_KTh[(size_t)(b*HD_ + d + 128)*S_ + s] = __float2half_rn(x2*c + x1*sn);
    }
    {
        const size_t o = (size_t)bs*HD_ + d;
        g_Vh[o]       = __float2half_rn(row[VOFF + d]);
        g_Vh[o + 128] = __float2half_rn(row[VOFF + d + 128]);
    }
}

// =====================================================================
// Tensor-core flash attention, fp16x2 (unchanged from R8).
// =====================================================================
#define QS_STR 264
#define KT_STR 72
#define VS_STR 136
#define ATT_Q_ELEMS  (128*QS_STR)
#define ATT_K_ELEMS  (2*64*KT_STR)
#define ATT_V_ELEMS  (64*VS_STR)
#define ATT2_SMEM_BYTES ((2*ATT_Q_ELEMS + ATT_K_ELEMS + ATT_V_ELEMS) * 2)

__device__ __forceinline__ void att_loadK(__half* Kb, int tid,
                                          int b, int jt, int kk, int buf)
{
#pragma unroll
    for (int i = 0; i < 2; ++i) {
        const int idx = tid + i*256;
        const int r = idx >> 3, c = (idx & 7) << 3;
        cpa16(&Kb[(buf*64 + r)*KT_STR + c],
              g_KTh + (size_t)(b*HD_ + kk*64 + r)*S_ + jt*64 + c);
    }
}
__device__ __forceinline__ void att_loadV(__half* Vb, int tid,
                                          int b, int jt, int vh)
{
#pragma unroll
    for (int i = 0; i < 4; ++i) {
        const int idx = tid + i*256;
        const int r = idx >> 4, c = (idx & 15) << 3;
        cpa16(&Vb[r*VS_STR + c],
              g_Vh + (size_t)(b*S_ + jt*64 + r)*HD_ + vh*128 + c);
    }
}

__global__ void __launch_bounds__(256, 1) attn_mma_kernel(const int* __restrict__ amask)
{
    extern __shared__ __align__(16) __half smb[];
    __shared__ int am[64];

    __half* Qh = smb;
    __half* Ql = smb + ATT_Q_ELEMS;
    __half* Kb = smb + 2*ATT_Q_ELEMS;
    __half* Vb = Kb + ATT_K_ELEMS;

    const int tid  = threadIdx.x;
    const int lane = tid & 31;
    const int warp = tid >> 5;

    const int bid = blockIdx.x;
    const int qt  = 15 - (bid >> 4);
    const int h   = bid & 7;
    const int b   = (bid >> 3) & 1;
    const int qbase = qt * 128;
    const int jt_max = 2*qt + 1;

#pragma unroll
    for (int i = 0; i < 32; ++i) {
        const int idx = tid + i*256;
        const int pl = idx >> 12, rem = idx & 4095;
        const int r = rem >> 5, c = (rem & 31) << 3;
        const __half* src = (pl ? g_Qlo : g_Qhi)
            + (size_t)(b*S_ + qbase + r)*D_ + h*HD_ + c;
        cpa16((pl ? Ql : Qh) + r*QS_STR + c, src);
    }
    CP_COMMIT();
    att_loadK(Kb, tid, b, 0, 0, 0);
    CP_COMMIT();

    float o[32][4];
#pragma unroll
    for (int i = 0; i < 32; ++i)
#pragma unroll
        for (int j = 0; j < 4; ++j) o[i][j] = 0.f;
    float m_lo = -1e30f, m_hi = -1e30f, l_lo = 0.f, l_hi = 0.f;

    const int rl = qbase + warp*16 + (lane >> 2);
    const int rh = rl + 8;

    for (int jt = 0; jt <= jt_max; ++jt) {
        const int kb = jt * 64;
        float s[8][4];
#pragma unroll
        for (int i = 0; i < 8; ++i)
#pragma unroll
            for (int j = 0; j < 4; ++j) s[i][j] = 0.f;

        for (int kk = 0; kk < 4; ++kk) {
            if (kk < 3) {
                att_loadK(Kb, tid, b, jt, kk + 1, (kk + 1) & 1);
                CP_COMMIT();
                CP_WAIT(1);
            } else {
                att_loadV(Vb, tid, b, jt, 0);
                CP_COMMIT();
                if (jt < jt_max) {
                    att_loadK(Kb, tid, b, jt + 1, 0, 0);
                    CP_COMMIT();
                    CP_WAIT(2);
                } else {
                    CP_WAIT(1);
                }
            }
            __syncthreads();
            if (kk == 0 && tid < 64) am[tid] = amask[b*S_ + kb + tid];

            const int buf = kk & 1;
#pragma unroll
            for (int ks = 0; ks < 4; ++ks) {
                unsigned qh_[4], ql_[4];
                const unsigned qaddr_off = (warp*16 + (lane & 15))*QS_STR
                                         + kk*64 + ks*16 + ((lane >> 4) << 3);
                ldsm_x4(qh_, sptr(Qh + qaddr_off));
                ldsm_x4(ql_, sptr(Ql + qaddr_off));
#pragma unroll
                for (int nf2 = 0; nf2 < 4; ++nf2) {
                    unsigned kh_[4];
                    const int koff = (ks*16 + (lane & 15))*KT_STR
                                   + nf2*16 + ((lane >> 4) << 3);
                    ldsm_x4t(kh_, sptr(Kb + buf*64*KT_STR + koff));
                    mma_f16(s[nf2*2],   qh_, kh_);
                    mma_f16(s[nf2*2],   ql_, kh_);
                    mma_f16(s[nf2*2+1], qh_, kh_ + 2);
                    mma_f16(s[nf2*2+1], ql_, kh_ + 2);
                }
            }
            __syncthreads();
        }

#pragma unroll
        for (int nf = 0; nf < 8; ++nf) {
#pragma unroll
            for (int j = 0; j < 2; ++j) {
                const int cl = nf*8 + (lane & 3)*2 + j;
                const int cg = kb + cl;
                const bool bad = (am[cl] == 0);
                if (bad || cg > rl) s[nf][j]     = -1e30f;
                if (bad || cg > rh) s[nf][2 + j] = -1e30f;
            }
        }
        float ml = -1e30f, mh = -1e30f;
#pragma unroll
        for (int nf = 0; nf < 8; ++nf) {
            ml = fmaxf(ml, fmaxf(s[nf][0], s[nf][1]));
            mh = fmaxf(mh, fmaxf(s[nf][2], s[nf][3]));
        }
        ml = fmaxf(ml, __shfl_xor_sync(0xffffffffu, ml, 1));
        ml = fmaxf(ml, __shfl_xor_sync(0xffffffffu, ml, 2));
        mh = fmaxf(mh, __shfl_xor_sync(0xffffffffu, mh, 1));
        mh = fmaxf(mh, __shfl_xor_sync(0xffffffffu, mh, 2));

        const float mnl = fmaxf(m_lo, ml);
        const float mnh = fmaxf(m_hi, mh);
        const float al = ex2(m_lo - mnl);
        const float ah = ex2(m_hi - mnh);
        m_lo = mnl; m_hi = mnh;

        float suml = 0.f, sumh = 0.f;
#pragma unroll
        for (int nf = 0; nf < 8; ++nf) {
            s[nf][0] = ex2(s[nf][0] - mnl);  suml += s[nf][0];
            s[nf][1] = ex2(s[nf][1] - mnl);  suml += s[nf][1];
            s[nf][2] = ex2(s[nf][2] - mnh);  sumh += s[nf][2];
            s[nf][3] = ex2(s[nf][3] - mnh);  sumh += s[nf][3];
        }
        suml += __shfl_xor_sync(0xffffffffu, suml, 1);
        suml += __shfl_xor_sync(0xffffffffu, suml, 2);
        sumh += __shfl_xor_sync(0xffffffffu, sumh, 1);
        sumh += __shfl_xor_sync(0xffffffffu, sumh, 2);
        l_lo = l_lo*al + suml;
        l_hi = l_hi*ah + sumh;
#pragma unroll
        for (int nf = 0; nf < 32; ++nf) {
            o[nf][0] *= al; o[nf][1] *= al;
            o[nf][2] *= ah; o[nf][3] *= ah;
        }

        unsigned pah[4][4], pal[4][4];
#pragma unroll
        for (int kk = 0; kk < 4; ++kk) {
            const int f0 = 2*kk, f1 = 2*kk + 1;
            split_pack_h(s[f0][0], s[f0][1], pah[kk][0], pal[kk][0]);
            split_pack_h(s[f0][2], s[f0][3], pah[kk][1], pal[kk][1]);
            split_pack_h(s[f1][0], s[f1][1], pah[kk][2], pal[kk][2]);
            split_pack_h(s[f1][2], s[f1][3], pah[kk][3], pal[kk][3]);
        }

        // ---- PV: half 0 ----
        if (jt < jt_max) { CP_WAIT(1); } else { CP_WAIT(0); }
        __syncthreads();
#pragma unroll
        for (int nf2 = 0; nf2 < 8; ++nf2) {
#pragma unroll
            for (int kk = 0; kk < 4; ++kk) {
                unsigned vh_[4];
                const int voff = (kk*16 + (lane & 15))*VS_STR
                               + nf2*16 + ((lane >> 4) << 3);
                ldsm_x4t(vh_, sptr(Vb + voff));
                const int o0 = nf2*2;
                mma_f16(o[o0],   pah[kk], vh_);
                mma_f16(o[o0],   pal[kk], vh_);
                mma_f16(o[o0+1], pah[kk], vh_ + 2);
                mma_f16(o[o0+1], pal[kk], vh_ + 2);
            }
        }
        __syncthreads();

        // ---- PV: half 1 ----
        att_loadV(Vb, tid, b, jt, 1);
        CP_COMMIT();
        CP_WAIT(0);
        __syncthreads();
#pragma unroll
        for (int nf2 = 0; nf2 < 8; ++nf2) {
#pragma unroll
            for (int kk = 0; kk < 4; ++kk) {
                unsigned vh_[4];
                const int voff = (kk*16 + (lane & 15))*VS_STR
                               + nf2*16 + ((lane >> 4) << 3);
                ldsm_x4t(vh_, sptr(Vb + voff));
                const int o0 = 16 + nf2*2;
                mma_f16(o[o0],   pah[kk], vh_);
                mma_f16(o[o0],   pal[kk], vh_);
                mma_f16(o[o0+1], pah[kk], vh_ + 2);
                mma_f16(o[o0+1], pal[kk], vh_ + 2);
            }
        }
        __syncthreads();
    }

    // ---- normalize, split to fp16 hi/lo, write AO for oproj ----
    const float invl = 1.f / l_lo;
    const float invh = 1.f / l_hi;
#pragma unroll
    for (int nf = 0; nf < 32; ++nf) {
        const int c = h*HD_ + nf*8 + (lane & 3)*2;
        const size_t il = (size_t)(b*S_ + rl)*D_ + c;
        const size_t ih = (size_t)(b*S_ + rh)*D_ + c;
        unsigned hi, lo;
        split_pack_h(o[nf][0]*invl, o[nf][1]*invl, hi, lo);
        *(unsigned*)&g_AOhi[il] = hi;
        *(unsigned*)&g_AOlo[il] = lo;
        split_pack_h(o[nf][2]*invh, o[nf][3]*invh, hi, lo);
        *(unsigned*)&g_AOhi[ih] = hi;
        *(unsigned*)&g_AOlo[ih] = lo;
    }
}

// =====================================================================
extern "C" void kernel_launch(void* const* d_in, const int* in_sizes, int n_in,
                              void* d_out, int out_size)
{
    (void)in_sizes; (void)n_in; (void)out_size;
    const float* X   = (const float*)d_in[0];
    const int*   am  = (const int*)  d_in[1];
    const int*   pos = (const int*)  d_in[2];
    const float* Wq  = (const float*)d_in[3];
    const float* Wk  = (const float*)d_in[4];
    const float* Wv  = (const float*)d_in[5];
    const float* Wo  = (const float*)d_in[6];
    float* out = (float*)d_out;

    cudaFuncSetAttribute(tc3_gemm_kernel,
                         cudaFuncAttributeMaxDynamicSharedMemorySize, GEMM3_SMEM);
    cudaFuncSetAttribute(attn_mma_kernel,
                         cudaFuncAttributeMaxDynamicSharedMemorySize, ATT2_SMEM_BYTES);

    __half *Xhi = 0, *Xlo = 0, *Wh = 0, *WOh = 0, *AOhi = 0, *AOlo = 0;
    float *qkv = 0;
    cudaGetSymbolAddress((void**)&Xhi,  g_Xhi);
    cudaGetSymbolAddress((void**)&Xlo,  g_Xlo);
    cudaGetSymbolAddress((void**)&Wh,   g_Wh);
    cudaGetSymbolAddress((void**)&WOh,  g_WOh);
    cudaGetSymbolAddress((void**)&AOhi, g_AOhi);
    cudaGetSymbolAddress((void**)&AOlo, g_AOlo);
    cudaGetSymbolAddress((void**)&qkv,  g_qkv);

    // 1. merged prep: X split fp16 hi/lo; W, Wo rounded fp16
    prep_kernel<<<(NX_ + NW_ + NWO_)/256, 256>>>(X, Wq, Wk, Wv, Wo);

    // 2. fused QKV projection (fp16x2): 128x128 tiles, 4:1 mma:ldsm
    tc3_gemm_kernel<<<dim3(NQKV/128, (B_*S_)/128), 256, GEMM3_SMEM>>>(
        Xhi, Xlo, Wh, qkv, NQKV, D_);

    // 3. RoPE + fp16 prep of Q (split, scaled), K^T, V
    rope_split_kernel<<<B_*S_, 128>>>(pos);

    // 4. tensor-core flash attention (fp16x2, writes AOhi/AOlo)
    attn_mma_kernel<<<256, 256, ATT2_SMEM_BYTES>>>(am);

    // 5. output projection (fp16x2): 128x128 tiles
    tc3_gemm_kernel<<<dim3(D_/128, (B_*S_)/128), 256, GEMM3_SMEM>>>(
        AOhi, AOlo, WOh, out, D_, D_);
}

// round 11
// speedup vs baseline: 5.2075x; 1.4897x over previous
#include <cuda_runtime.h>
#include <cuda_fp16.h>
#include <stdint.h>
#include <cstdint>
#include <math.h>

#define B_  2
#define S_  2048
#define D_  2048
#define H_  8
#define HD_ 256
#define NQKV 2560          // 2048 Q + 256 K + 256 V
#define KOFF 2048
#define VOFF 2304

// ---- scratch (static device globals; no allocation) ----
__device__ float g_qkv[B_*S_*NQKV];     // [4096, 2560] fp32 (Q|K|V)

__device__ __half g_Xh  [B_*S_*D_];     // X rounded fp16
__device__ __half g_Wh  [D_*NQKV];      // W rounded fp16
__device__ __half g_WOh [D_*D_];
__device__ __half g_AOh [B_*S_*D_];     // attn output rounded fp16

// attention operands, written by rope_split
__device__ __half g_Qhi [B_*S_*D_];     // [4096][2048], pre-scaled, split
__device__ __half g_Qlo [B_*S_*D_];
__device__ __half g_KTh [B_*HD_*S_];    // [b][hd 256][S 2048] (K^T), rounded
__device__ __half g_Vh  [B_*S_*HD_];    // [4096][256], rounded

// =====================================================================
// helpers
// =====================================================================
__device__ __forceinline__ unsigned sptr(const void* p) {
    return (unsigned)__cvta_generic_to_shared(p);
}
__device__ __forceinline__ void cpa16(void* dst, const void* src) {
    asm volatile("cp.async.cg.shared.global [%0], [%1], 16;\n"
                 :: "r"(sptr(dst)), "l"(src));
}
#define CP_COMMIT() asm volatile("cp.async.commit_group;\n")
#define CP_WAIT(N)  asm volatile("cp.async.wait_group %0;\n" :: "n"(N))

__device__ __forceinline__ void ldsm_x4(unsigned* r, unsigned a) {
    asm volatile("ldmatrix.sync.aligned.m8n8.x4.shared.b16 {%0,%1,%2,%3},[%4];"
                 : "=r"(r[0]), "=r"(r[1]), "=r"(r[2]), "=r"(r[3]) : "r"(a));
}
__device__ __forceinline__ void ldsm_x4t(unsigned* r, unsigned a) {
    asm volatile("ldmatrix.sync.aligned.m8n8.x4.trans.shared.b16 {%0,%1,%2,%3},[%4];"
                 : "=r"(r[0]), "=r"(r[1]), "=r"(r[2]), "=r"(r[3]) : "r"(a));
}
__device__ __forceinline__ void mma_f16(float* d, const unsigned* a, const unsigned* b) {
    asm volatile("mma.sync.aligned.m16n8k16.row.col.f32.f16.f16.f32 "
                 "{%0,%1,%2,%3},{%4,%5,%6,%7},{%8,%9},{%0,%1,%2,%3};"
                 : "+f"(d[0]), "+f"(d[1]), "+f"(d[2]), "+f"(d[3])
                 : "r"(a[0]), "r"(a[1]), "r"(a[2]), "r"(a[3]),
                   "r"(b[0]), "r"(b[1]));
}
__device__ __forceinline__ void split1h(float x, __half& h, __half& l) {
    h = __float2half_rn(x);
    l = __float2half_rn(x - __half2float(h));
}
__device__ __forceinline__ float ex2(float x) {
    float y; asm("ex2.approx.f32 %0, %1;" : "=f"(y) : "f"(x)); return y;
}
__device__ __forceinline__ void split_pack_h(float a, float b, unsigned& hi, unsigned& lo) {
    __half ah, al, bh, bl;
    split1h(a, ah, al); split1h(b, bh, bl);
    __half2 th = __halves2half2(ah, bh);
    __half2 tl = __halves2half2(al, bl);
    hi = *reinterpret_cast<unsigned*>(&th);
    lo = *reinterpret_cast<unsigned*>(&tl);
}
__device__ __forceinline__ unsigned pack_h2(float a, float b) {
    __half2 t = __halves2half2(__float2half_rn(a), __float2half_rn(b));
    return *reinterpret_cast<unsigned*>(&t);
}

// =====================================================================
// merged prep: X round; Wqkv round; Wo round — one launch
// =====================================================================
#define NX_  (B_*S_*D_)
#define NW_  (D_*NQKV)
#define NWO_ (D_*D_)

__global__ void prep_kernel(const float* __restrict__ X,
                            const float* __restrict__ Wq,
                            const float* __restrict__ Wk,
                            const float* __restrict__ Wv,
                            const float* __restrict__ Wo)
{
    int i = blockIdx.x * 256 + threadIdx.x;
    if (i < NX_) {
        g_Xh[i] = __float2half_rn(X[i]);
    } else if (i < NX_ + NW_) {
        const int j = i - NX_;
        const int row = j / NQKV, col = j % NQKV;
        float x;
        if (col < KOFF)       x = Wq[row * (H_*HD_) + col];
        else if (col < VOFF)  x = Wk[row * HD_ + (col - KOFF)];
        else                  x = Wv[row * HD_ + (col - VOFF)];
        g_Wh[j] = __float2half_rn(x);
    } else {
        const int j = i - NX_ - NW_;
        g_WOh[j] = __float2half_rn(Wo[j]);
    }
}

// =====================================================================
// fp16 tensor-core GEMM: A rounded, B rounded (single planes).
// BM=128 x BN=128, K-step 32, 256 threads = 8 warps 4(M) x 2(N);
// warp tile 32x64; B frags via ldsm_x4t.
// =====================================================================
#define AS2i(buf,r,c) ((((buf)*128 + (r))*40) + (c))
#define BSTR3 136
#define BSi3(buf,r,c) ((((buf)*32 + (r))*BSTR3) + (c))
#define GEMM4_AS_BYTES (2*128*40*2)                 // 20480
#define GEMM4_SMEM (GEMM4_AS_BYTES + 2*32*BSTR3*2)  // 37888

__global__ void __launch_bounds__(256, 2) tc4_gemm_kernel(
    const __half* __restrict__ Ah, const __half* __restrict__ Bh,
    float* __restrict__ C, const int N, const int K)
{
    extern __shared__ __align__(16) char smem_raw[];
    __half* As = (__half*)(smem_raw);
    __half* Bs = (__half*)(smem_raw + GEMM4_AS_BYTES);

    const int tid  = threadIdx.x;
    const int brow = blockIdx.y * 128;
    const int bcol = blockIdx.x * 128;
    const int lane = tid & 31;
    const int warp = tid >> 5;
    const int wm   = (warp & 3) * 32;
    const int wn   = (warp >> 2) * 64;

    auto load_stage = [&](int t, int buf) {
        const int k0 = t * 32;
#pragma unroll
        for (int i = 0; i < 2; ++i) {          // A: 128x32
            const int idx = tid + i * 256;
            const int ra = idx >> 2,  ca = (idx & 3) << 3;
            cpa16(&As[AS2i(buf, ra, ca)],
                  Ah + (size_t)(brow + ra) * K + k0 + ca);
        }
#pragma unroll
        for (int i = 0; i < 2; ++i) {          // B: 32x128
            const int idx = tid + i * 256;
            const int rb = idx >> 4, cb = (idx & 15) << 3;
            cpa16(&Bs[BSi3(buf, rb, cb)],
                  Bh + (size_t)(k0 + rb) * N + bcol + cb);
        }
    };

    float acc[2][8][4];
#pragma unroll
    for (int i = 0; i < 2; ++i)
#pragma unroll
        for (int j = 0; j < 8; ++j)
#pragma unroll
            for (int u = 0; u < 4; ++u) acc[i][j][u] = 0.f;

    const int ntiles = K >> 5;
    load_stage(0, 0);
    CP_COMMIT();

    for (int t = 0; t < ntiles; ++t) {
        if (t + 1 < ntiles) {
            load_stage(t + 1, (t + 1) & 1);
            CP_COMMIT();
            CP_WAIT(1);
        } else {
            CP_WAIT(0);
        }
        __syncthreads();
        const int buf = t & 1;

#pragma unroll
        for (int ks = 0; ks < 32; ks += 16) {
            unsigned bf[4][4];
#pragma unroll
            for (int nt2 = 0; nt2 < 4; ++nt2)
                ldsm_x4t(bf[nt2], sptr(&Bs[BSi3(buf, ks + (lane & 15),
                                        wn + nt2*16 + ((lane >> 4) << 3))]));
#pragma unroll
            for (int mt = 0; mt < 2; ++mt) {
                unsigned ah[4];
                const int ar = wm + mt*16 + (lane & 15);
                const int ac = ks + ((lane >> 4) << 3);
                ldsm_x4(ah, sptr(&As[AS2i(buf, ar, ac)]));
#pragma unroll
                for (int nt2 = 0; nt2 < 4; ++nt2) {
                    mma_f16(acc[mt][2*nt2],   ah, bf[nt2]);
                    mma_f16(acc[mt][2*nt2+1], ah, bf[nt2] + 2);
                }
            }
        }
        __syncthreads();
    }

#pragma unroll
    for (int mt = 0; mt < 2; ++mt) {
#pragma unroll
        for (int nt = 0; nt < 8; ++nt) {
            const int r0 = brow + wm + mt*16 + (lane >> 2);
            const int c0 = bcol + wn + nt*8 + ((lane & 3) << 1);
            *(float2*)&C[(size_t)r0 * N + c0]       = make_float2(acc[mt][nt][0], acc[mt][nt][1]);
            *(float2*)&C[(size_t)(r0 + 8) * N + c0] = make_float2(acc[mt][nt][2], acc[mt][nt][3]);
        }
    }
}

// =====================================================================
// RoPE + fp16 prep: Q split (scaled), K^T rounded, V rounded.
// =====================================================================
__global__ void rope_split_kernel(const int* __restrict__ pos_ids)
{
    const int bs = blockIdx.x;
    const int d  = threadIdx.x;
    const int b  = bs >> 11;
    const int s  = bs & 2047;
    const int p  = pos_ids[bs];

    const double inv = exp(-((double)d / 128.0) * log(10000.0));
    const double ang = (double)p * inv;
    const float c  = (float)cos(ang);
    const float sn = (float)sin(ang);

    const float qsc = 0.0625f * 1.4426950408889634f;

    const float* row = g_qkv + (size_t)bs * NQKV;
#pragma unroll
    for (int h = 0; h < H_; ++h) {
        const float x1 = row[h*HD_ + d], x2 = row[h*HD_ + d + 128];
        const float r1 = (x1*c - x2*sn) * qsc;
        const float r2 = (x2*c + x1*sn) * qsc;
        __half hh, ll;
        const size_t o1 = (size_t)bs*D_ + h*HD_ + d;
        split1h(r1, hh, ll); g_Qhi[o1] = hh; g_Qlo[o1] = ll;
        split1h(r2, hh, ll); g_Qhi[o1+128] = hh; g_Qlo[o1+128] = ll;
    }
    {
        const float x1 = row[KOFF + d], x2 = row[KOFF + d + 128];
        g_KTh[(size_t)(b*HD_ + d)*S_ + s]       = __float2half_rn(x1*c - x2*sn);
        g_KTh[(size_t)(b*HD_ + d + 128)*S_ + s] = __float2half_rn(x2*c + x1*sn);
    }
    {
        const size_t o = (size_t)bs*HD_ + d;
        g_Vh[o]       = __float2half_rn(row[VOFF + d]);
        g_Vh[o + 128] = __float2half_rn(row[VOFF + d + 128]);
    }
}

// =====================================================================
// Tensor-core flash attention, fp16x2 (unchanged core; epilogue writes
// single rounded fp16 AO).
// =====================================================================
#define QS_STR 264
#define KT_STR 72
#define VS_STR 136
#define ATT_Q_ELEMS  (128*QS_STR)
#define ATT_K_ELEMS  (2*64*KT_STR)
#define ATT_V_ELEMS  (64*VS_STR)
#define ATT2_SMEM_BYTES ((2*ATT_Q_ELEMS + ATT_K_ELEMS + ATT_V_ELEMS) * 2)

__device__ __forceinline__ void att_loadK(__half* Kb, int tid,
                                          int b, int jt, int kk, int buf)
{
#pragma unroll
    for (int i = 0; i < 2; ++i) {
        const int idx = tid + i*256;
        const int r = idx >> 3, c = (idx & 7) << 3;
        cpa16(&Kb[(buf*64 + r)*KT_STR + c],
              g_KTh + (size_t)(b*HD_ + kk*64 + r)*S_ + jt*64 + c);
    }
}
__device__ __forceinline__ void att_loadV(__half* Vb, int tid,
                                          int b, int jt, int vh)
{
#pragma unroll
    for (int i = 0; i < 4; ++i) {
        const int idx = tid + i*256;
        const int r = idx >> 4, c = (idx & 15) << 3;
        cpa16(&Vb[r*VS_STR + c],
              g_Vh + (size_t)(b*S_ + jt*64 + r)*HD_ + vh*128 + c);
    }
}

__global__ void __launch_bounds__(256, 1) attn_mma_kernel(const int* __restrict__ amask)
{
    extern __shared__ __align__(16) __half smb[];
    __shared__ int am[64];

    __half* Qh = smb;
    __half* Ql = smb + ATT_Q_ELEMS;
    __half* Kb = smb + 2*ATT_Q_ELEMS;
    __half* Vb = Kb + ATT_K_ELEMS;

    const int tid  = threadIdx.x;
    const int lane = tid & 31;
    const int warp = tid >> 5;

    const int bid = blockIdx.x;
    const int qt  = 15 - (bid >> 4);
    const int h   = bid & 7;
    const int b   = (bid >> 3) & 1;
    const int qbase = qt * 128;
    const int jt_max = 2*qt + 1;

#pragma unroll
    for (int i = 0; i < 32; ++i) {
        const int idx = tid + i*256;
        const int pl = idx >> 12, rem = idx & 4095;
        const int r = rem >> 5, c = (rem & 31) << 3;
        const __half* src = (pl ? g_Qlo : g_Qhi)
            + (size_t)(b*S_ + qbase + r)*D_ + h*HD_ + c;
        cpa16((pl ? Ql : Qh) + r*QS_STR + c, src);
    }
    CP_COMMIT();
    att_loadK(Kb, tid, b, 0, 0, 0);
    CP_COMMIT();

    float o[32][4];
#pragma unroll
    for (int i = 0; i < 32; ++i)
#pragma unroll
        for (int j = 0; j < 4; ++j) o[i][j] = 0.f;
    float m_lo = -1e30f, m_hi = -1e30f, l_lo = 0.f, l_hi = 0.f;

    const int rl = qbase + warp*16 + (lane >> 2);
    const int rh = rl + 8;

    for (int jt = 0; jt <= jt_max; ++jt) {
        const int kb = jt * 64;
        float s[8][4];
#pragma unroll
        for (int i = 0; i < 8; ++i)
#pragma unroll
            for (int j = 0; j < 4; ++j) s[i][j] = 0.f;

        for (int kk = 0; kk < 4; ++kk) {
            if (kk < 3) {
                att_loadK(Kb, tid, b, jt, kk + 1, (kk + 1) & 1);
                CP_COMMIT();
                CP_WAIT(1);
            } else {
                att_loadV(Vb, tid, b, jt, 0);
                CP_COMMIT();
                if (jt < jt_max) {
                    att_loadK(Kb, tid, b, jt + 1, 0, 0);
                    CP_COMMIT();
                    CP_WAIT(2);
                } else {
                    CP_WAIT(1);
                }
            }
            __syncthreads();
            if (kk == 0 && tid < 64) am[tid] = amask[b*S_ + kb + tid];

            const int buf = kk & 1;
#pragma unroll
            for (int ks = 0; ks < 4; ++ks) {
                unsigned qh_[4], ql_[4];
                const unsigned qaddr_off = (warp*16 + (lane & 15))*QS_STR
                                         + kk*64 + ks*16 + ((lane >> 4) << 3);
                ldsm_x4(qh_, sptr(Qh + qaddr_off));
                ldsm_x4(ql_, sptr(Ql + qaddr_off));
#pragma unroll
                for (int nf2 = 0; nf2 < 4; ++nf2) {
                    unsigned kh_[4];
                    const int koff = (ks*16 + (lane & 15))*KT_STR
                                   + nf2*16 + ((lane >> 4) << 3);
                    ldsm_x4t(kh_, sptr(Kb + buf*64*KT_STR + koff));
                    mma_f16(s[nf2*2],   qh_, kh_);
                    mma_f16(s[nf2*2],   ql_, kh_);
                    mma_f16(s[nf2*2+1], qh_, kh_ + 2);
                    mma_f16(s[nf2*2+1], ql_, kh_ + 2);
                }
            }
            __syncthreads();
        }

#pragma unroll
        for (int nf = 0; nf < 8; ++nf) {
#pragma unroll
            for (int j = 0; j < 2; ++j) {
                const int cl = nf*8 + (lane & 3)*2 + j;
                const int cg = kb + cl;
                const bool bad = (am[cl] == 0);
                if (bad || cg > rl) s[nf][j]     = -1e30f;
                if (bad || cg > rh) s[nf][2 + j] = -1e30f;
            }
        }
        float ml = -1e30f, mh = -1e30f;
#pragma unroll
        for (int nf = 0; nf < 8; ++nf) {
            ml = fmaxf(ml, fmaxf(s[nf][0], s[nf][1]));
            mh = fmaxf(mh, fmaxf(s[nf][2], s[nf][3]));
        }
        ml = fmaxf(ml, __shfl_xor_sync(0xffffffffu, ml, 1));
        ml = fmaxf(ml, __shfl_xor_sync(0xffffffffu, ml, 2));
        mh = fmaxf(mh, __shfl_xor_sync(0xffffffffu, mh, 1));
        mh = fmaxf(mh, __shfl_xor_sync(0xffffffffu, mh, 2));

        const float mnl = fmaxf(m_lo, ml);
        const float mnh = fmaxf(m_hi, mh);
        const float al = ex2(m_lo - mnl);
        const float ah = ex2(m_hi - mnh);
        m_lo = mnl; m_hi = mnh;

        float suml = 0.f, sumh = 0.f;
#pragma unroll
        for (int nf = 0; nf < 8; ++nf) {
            s[nf][0] = ex2(s[nf][0] - mnl);  suml += s[nf][0];
            s[nf][1] = ex2(s[nf][1] - mnl);  suml += s[nf][1];
            s[nf][2] = ex2(s[nf][2] - mnh);  sumh += s[nf][2];
            s[nf][3] = ex2(s[nf][3] - mnh);  sumh += s[nf][3];
        }
        suml += __shfl_xor_sync(0xffffffffu, suml, 1);
        suml += __shfl_xor_sync(0xffffffffu, suml, 2);
        sumh += __shfl_xor_sync(0xffffffffu, sumh, 1);
        sumh += __shfl_xor_sync(0xffffffffu, sumh, 2);
        l_lo = l_lo*al + suml;
        l_hi = l_hi*ah + sumh;
#pragma unroll
        for (int nf = 0; nf < 32; ++nf) {
            o[nf][0] *= al; o[nf][1] *= al;
            o[nf][2] *= ah; o[nf][3] *= ah;
        }

        unsigned pah[4][4], pal[4][4];
#pragma unroll
        for (int kk = 0; kk < 4; ++kk) {
            const int f0 = 2*kk, f1 = 2*kk + 1;
            split_pack_h(s[f0][0], s[f0][1], pah[kk][0], pal[kk][0]);
            split_pack_h(s[f0][2], s[f0][3], pah[kk][1], pal[kk][1]);
            split_pack_h(s[f1][0], s[f1][1], pah[kk][2], pal[kk][2]);
            split_pack_h(s[f1][2], s[f1][3], pah[kk][3], pal[kk][3]);
        }

        // ---- PV: half 0 ----
        if (jt < jt_max) { CP_WAIT(1); } else { CP_WAIT(0); }
        __syncthreads();
#pragma unroll
        for (int nf2 = 0; nf2 < 8; ++nf2) {
#pragma unroll
            for (int kk = 0; kk < 4; ++kk) {
                unsigned vh_[4];
                const int voff = (kk*16 + (lane & 15))*VS_STR
                               + nf2*16 + ((lane >> 4) << 3);
                ldsm_x4t(vh_, sptr(Vb + voff));
                const int o0 = nf2*2;
                mma_f16(o[o0],   pah[kk], vh_);
                mma_f16(o[o0],   pal[kk], vh_);
                mma_f16(o[o0+1], pah[kk], vh_ + 2);
                mma_f16(o[o0+1], pal[kk], vh_ + 2);
            }
        }
        __syncthreads();

        // ---- PV: half 1 ----
        att_loadV(Vb, tid, b, jt, 1);
        CP_COMMIT();
        CP_WAIT(0);
        __syncthreads();
#pragma unroll
        for (int nf2 = 0; nf2 < 8; ++nf2) {
#pragma unroll
            for (int kk = 0; kk < 4; ++kk) {
                unsigned vh_[4];
                const int voff = (kk*16 + (lane & 15))*VS_STR
                               + nf2*16 + ((lane >> 4) << 3);
                ldsm_x4t(vh_, sptr(Vb + voff));
                const int o0 = 16 + nf2*2;
                mma_f16(o[o0],   pah[kk], vh_);
                mma_f16(o[o0],   pal[kk], vh_);
                mma_f16(o[o0+1], pah[kk], vh_ + 2);
                mma_f16(o[o0+1], pal[kk], vh_ + 2);
            }
        }
        __syncthreads();
    }

    // ---- normalize, round to fp16, write AO for oproj ----
    const float invl = 1.f / l_lo;
    const float invh = 1.f / l_hi;
#pragma unroll
    for (int nf = 0; nf < 32; ++nf) {
        const int c = h*HD_ + nf*8 + (lane & 3)*2;
        *(unsigned*)&g_AOh[(size_t)(b*S_ + rl)*D_ + c] =
            pack_h2(o[nf][0]*invl, o[nf][1]*invl);
        *(unsigned*)&g_AOh[(size_t)(b*S_ + rh)*D_ + c] =
            pack_h2(o[nf][2]*invh, o[nf][3]*invh);
    }
}

// =====================================================================
extern "C" void kernel_launch(void* const* d_in, const int* in_sizes, int n_in,
                              void* d_out, int out_size)
{
    (void)in_sizes; (void)n_in; (void)out_size;
    const float* X   = (const float*)d_in[0];
    const int*   am  = (const int*)  d_in[1];
    const int*   pos = (const int*)  d_in[2];
    const float* Wq  = (const float*)d_in[3];
    const float* Wk  = (const float*)d_in[4];
    const float* Wv  = (const float*)d_in[5];
    const float* Wo  = (const float*)d_in[6];
    float* out = (float*)d_out;

    cudaFuncSetAttribute(tc4_gemm_kernel,
                         cudaFuncAttributeMaxDynamicSharedMemorySize, GEMM4_SMEM);
    cudaFuncSetAttribute(attn_mma_kernel,
                         cudaFuncAttributeMaxDynamicSharedMemorySize, ATT2_SMEM_BYTES);

    __half *Xh = 0, *Wh = 0, *WOh = 0, *AOh = 0;
    float *qkv = 0;
    cudaGetSymbolAddress((void**)&Xh,  g_Xh);
    cudaGetSymbolAddress((void**)&Wh,  g_Wh);
    cudaGetSymbolAddress((void**)&WOh, g_WOh);
    cudaGetSymbolAddress((void**)&AOh, g_AOh);
    cudaGetSymbolAddress((void**)&qkv, g_qkv);

    // 1. merged prep: X, W, Wo rounded fp16
    prep_kernel<<<(NX_ + NW_ + NWO_)/256, 256>>>(X, Wq, Wk, Wv, Wo);

    // 2. fused QKV projection (fp16): 128x128 tiles
    tc4_gemm_kernel<<<dim3(NQKV/128, (B_*S_)/128), 256, GEMM4_SMEM>>>(
        Xh, Wh, qkv, NQKV, D_);

    // 3. RoPE + fp16 prep of Q (split, scaled), K^T, V
    rope_split_kernel<<<B_*S_, 128>>>(pos);

    // 4. tensor-core flash attention (fp16x2, writes AOh)
    attn_mma_kernel<<<256, 256, ATT2_SMEM_BYTES>>>(am);

    // 5. output projection (fp16): 128x128 tiles
    tc4_gemm_kernel<<<dim3(D_/128, (B_*S_)/128), 256, GEMM4_SMEM>>>(
        AOh, WOh, out, D_, D_);
}

// round 12
// speedup vs baseline: 5.7755x; 1.1091x over previous
#include <cuda_runtime.h>
#include <cuda_fp16.h>
#include <stdint.h>
#include <cstdint>
#include <math.h>

#define B_  2
#define S_  2048
#define D_  2048
#define H_  8
#define HD_ 256
#define NQKV 2560          // 2048 Q + 256 K + 256 V
#define KOFF 2048
#define VOFF 2304

// ---- scratch (static device globals; no allocation) ----
__device__ float g_qkv[B_*S_*NQKV];     // [4096, 2560] fp32 (Q|K|V)

__device__ __half g_Xh  [B_*S_*D_];     // X rounded fp16
__device__ __half g_Wh  [D_*NQKV];      // W rounded fp16
__device__ __half g_WOh [D_*D_];
__device__ __half g_AOh [B_*S_*D_];     // attn output rounded fp16

// attention operands, written by rope_split
__device__ __half g_Qh  [B_*S_*D_];     // [4096][2048], pre-scaled, rounded
__device__ __half g_KTh [B_*HD_*S_];    // [b][hd 256][S 2048] (K^T), rounded
__device__ __half g_Vh  [B_*S_*HD_];    // [4096][256], rounded

// =====================================================================
// helpers
// =====================================================================
__device__ __forceinline__ unsigned sptr(const void* p) {
    return (unsigned)__cvta_generic_to_shared(p);
}
__device__ __forceinline__ void cpa16(void* dst, const void* src) {
    asm volatile("cp.async.cg.shared.global [%0], [%1], 16;\n"
                 :: "r"(sptr(dst)), "l"(src));
}
#define CP_COMMIT() asm volatile("cp.async.commit_group;\n")
#define CP_WAIT(N)  asm volatile("cp.async.wait_group %0;\n" :: "n"(N))

__device__ __forceinline__ void ldsm_x4(unsigned* r, unsigned a) {
    asm volatile("ldmatrix.sync.aligned.m8n8.x4.shared.b16 {%0,%1,%2,%3},[%4];"
                 : "=r"(r[0]), "=r"(r[1]), "=r"(r[2]), "=r"(r[3]) : "r"(a));
}
__device__ __forceinline__ void ldsm_x4t(unsigned* r, unsigned a) {
    asm volatile("ldmatrix.sync.aligned.m8n8.x4.trans.shared.b16 {%0,%1,%2,%3},[%4];"
                 : "=r"(r[0]), "=r"(r[1]), "=r"(r[2]), "=r"(r[3]) : "r"(a));
}
__device__ __forceinline__ void mma_f16(float* d, const unsigned* a, const unsigned* b) {
    asm volatile("mma.sync.aligned.m16n8k16.row.col.f32.f16.f16.f32 "
                 "{%0,%1,%2,%3},{%4,%5,%6,%7},{%8,%9},{%0,%1,%2,%3};"
                 : "+f"(d[0]), "+f"(d[1]), "+f"(d[2]), "+f"(d[3])
                 : "r"(a[0]), "r"(a[1]), "r"(a[2]), "r"(a[3]),
                   "r"(b[0]), "r"(b[1]));
}
__device__ __forceinline__ float ex2(float x) {
    float y; asm("ex2.approx.f32 %0, %1;" : "=f"(y) : "f"(x)); return y;
}
__device__ __forceinline__ unsigned pack_h2(float a, float b) {
    __half2 t = __halves2half2(__float2half_rn(a), __float2half_rn(b));
    return *reinterpret_cast<unsigned*>(&t);
}

// =====================================================================
// merged prep: X round; Wqkv round; Wo round — one launch
// =====================================================================
#define NX_  (B_*S_*D_)
#define NW_  (D_*NQKV)
#define NWO_ (D_*D_)

__global__ void prep_kernel(const float* __restrict__ X,
                            const float* __restrict__ Wq,
                            const float* __restrict__ Wk,
                            const float* __restrict__ Wv,
                            const float* __restrict__ Wo)
{
    int i = blockIdx.x * 256 + threadIdx.x;
    if (i < NX_) {
        g_Xh[i] = __float2half_rn(X[i]);
    } else if (i < NX_ + NW_) {
        const int j = i - NX_;
        const int row = j / NQKV, col = j % NQKV;
        float x;
        if (col < KOFF)       x = Wq[row * (H_*HD_) + col];
        else if (col < VOFF)  x = Wk[row * HD_ + (col - KOFF)];
        else                  x = Wv[row * HD_ + (col - VOFF)];
        g_Wh[j] = __float2half_rn(x);
    } else {
        const int j = i - NX_ - NW_;
        g_WOh[j] = __float2half_rn(Wo[j]);
    }
}

// =====================================================================
// fp16 tensor-core GEMM (proven R11): BM=128 x BN=128, K-step 32.
// =====================================================================
#define AS2i(buf,r,c) ((((buf)*128 + (r))*40) + (c))
#define BSTR3 136
#define BSi3(buf,r,c) ((((buf)*32 + (r))*BSTR3) + (c))
#define GEMM4_AS_BYTES (2*128*40*2)                 // 20480
#define GEMM4_SMEM (GEMM4_AS_BYTES + 2*32*BSTR3*2)  // 37888

__global__ void __launch_bounds__(256, 2) tc4_gemm_kernel(
    const __half* __restrict__ Ah, const __half* __restrict__ Bh,
    float* __restrict__ C, const int N, const int K)
{
    extern __shared__ __align__(16) char smem_raw[];
    __half* As = (__half*)(smem_raw);
    __half* Bs = (__half*)(smem_raw + GEMM4_AS_BYTES);

    const int tid  = threadIdx.x;
    const int brow = blockIdx.y * 128;
    const int bcol = blockIdx.x * 128;
    const int lane = tid & 31;
    const int warp = tid >> 5;
    const int wm   = (warp & 3) * 32;
    const int wn   = (warp >> 2) * 64;

    auto load_stage = [&](int t, int buf) {
        const int k0 = t * 32;
#pragma unroll
        for (int i = 0; i < 2; ++i) {          // A: 128x32
            const int idx = tid + i * 256;
            const int ra = idx >> 2,  ca = (idx & 3) << 3;
            cpa16(&As[AS2i(buf, ra, ca)],
                  Ah + (size_t)(brow + ra) * K + k0 + ca);
        }
#pragma unroll
        for (int i = 0; i < 2; ++i) {          // B: 32x128
            const int idx = tid + i * 256;
            const int rb = idx >> 4, cb = (idx & 15) << 3;
            cpa16(&Bs[BSi3(buf, rb, cb)],
                  Bh + (size_t)(k0 + rb) * N + bcol + cb);
        }
    };

    float acc[2][8][4];
#pragma unroll
    for (int i = 0; i < 2; ++i)
#pragma unroll
        for (int j = 0; j < 8; ++j)
#pragma unroll
            for (int u = 0; u < 4; ++u) acc[i][j][u] = 0.f;

    const int ntiles = K >> 5;
    load_stage(0, 0);
    CP_COMMIT();

    for (int t = 0; t < ntiles; ++t) {
        if (t + 1 < ntiles) {
            load_stage(t + 1, (t + 1) & 1);
            CP_COMMIT();
            CP_WAIT(1);
        } else {
            CP_WAIT(0);
        }
        __syncthreads();
        const int buf = t & 1;

#pragma unroll
        for (int ks = 0; ks < 32; ks += 16) {
            unsigned bf[4][4];
#pragma unroll
            for (int nt2 = 0; nt2 < 4; ++nt2)
                ldsm_x4t(bf[nt2], sptr(&Bs[BSi3(buf, ks + (lane & 15),
                                        wn + nt2*16 + ((lane >> 4) << 3))]));
#pragma unroll
            for (int mt = 0; mt < 2; ++mt) {
                unsigned ah[4];
                const int ar = wm + mt*16 + (lane & 15);
                const int ac = ks + ((lane >> 4) << 3);
                ldsm_x4(ah, sptr(&As[AS2i(buf, ar, ac)]));
#pragma unroll
                for (int nt2 = 0; nt2 < 4; ++nt2) {
                    mma_f16(acc[mt][2*nt2],   ah, bf[nt2]);
                    mma_f16(acc[mt][2*nt2+1], ah, bf[nt2] + 2);
                }
            }
        }
        __syncthreads();
    }

#pragma unroll
    for (int mt = 0; mt < 2; ++mt) {
#pragma unroll
        for (int nt = 0; nt < 8; ++nt) {
            const int r0 = brow + wm + mt*16 + (lane >> 2);
            const int c0 = bcol + wn + nt*8 + ((lane & 3) << 1);
            *(float2*)&C[(size_t)r0 * N + c0]       = make_float2(acc[mt][nt][0], acc[mt][nt][1]);
            *(float2*)&C[(size_t)(r0 + 8) * N + c0] = make_float2(acc[mt][nt][2], acc[mt][nt][3]);
        }
    }
}

// =====================================================================
// RoPE + fp16 prep: Q rounded (scaled), K^T rounded, V rounded.
// =====================================================================
__global__ void rope_split_kernel(const int* __restrict__ pos_ids)
{
    const int bs = blockIdx.x;
    const int d  = threadIdx.x;
    const int b  = bs >> 11;
    const int s  = bs & 2047;
    const int p  = pos_ids[bs];

    const double inv = exp(-((double)d / 128.0) * log(10000.0));
    const double ang = (double)p * inv;
    const float c  = (float)cos(ang);
    const float sn = (float)sin(ang);

    const float qsc = 0.0625f * 1.4426950408889634f;

    const float* row = g_qkv + (size_t)bs * NQKV;
#pragma unroll
    for (int h = 0; h < H_; ++h) {
        const float x1 = row[h*HD_ + d], x2 = row[h*HD_ + d + 128];
        const size_t o1 = (size_t)bs*D_ + h*HD_ + d;
        g_Qh[o1]       = __float2half_rn((x1*c - x2*sn) * qsc);
        g_Qh[o1 + 128] = __float2half_rn((x2*c + x1*sn) * qsc);
    }
    {
        const float x1 = row[KOFF + d], x2 = row[KOFF + d + 128];
        g_KTh[(size_t)(b*HD_ + d)*S_ + s]       = __float2half_rn(x1*c - x2*sn);
        g_KTh[(size_t)(b*HD_ + d + 128)*S_ + s] = __float2half_rn(x2*c + x1*sn);
    }
    {
        const size_t o = (size_t)bs*HD_ + d;
        g_Vh[o]       = __float2half_rn(row[VOFF + d]);
        g_Vh[o + 128] = __float2half_rn(row[VOFF + d + 128]);
    }
}

// =====================================================================
// Tensor-core flash attention, pure fp16 (Q, K, P, V single planes).
// BM=128 q, BN=64 k, 8 warps, Q resident.
// =====================================================================
#define QS_STR 264
#define KT_STR 72
#define VS_STR 136
#define ATT_Q_ELEMS  (128*QS_STR)
#define ATT_K_ELEMS  (2*64*KT_STR)
#define ATT_V_ELEMS  (64*VS_STR)
#define ATT3_SMEM_BYTES ((ATT_Q_ELEMS + ATT_K_ELEMS + ATT_V_ELEMS) * 2)

__device__ __forceinline__ void att_loadK(__half* Kb, int tid,
                                          int b, int jt, int kk, int buf)
{
#pragma unroll
    for (int i = 0; i < 2; ++i) {
        const int idx = tid + i*256;
        const int r = idx >> 3, c = (idx & 7) << 3;
        cpa16(&Kb[(buf*64 + r)*KT_STR + c],
              g_KTh + (size_t)(b*HD_ + kk*64 + r)*S_ + jt*64 + c);
    }
}
__device__ __forceinline__ void att_loadV(__half* Vb, int tid,
                                          int b, int jt, int vh)
{
#pragma unroll
    for (int i = 0; i < 4; ++i) {
        const int idx = tid + i*256;
        const int r = idx >> 4, c = (idx & 15) << 3;
        cpa16(&Vb[r*VS_STR + c],
              g_Vh + (size_t)(b*S_ + jt*64 + r)*HD_ + vh*128 + c);
    }
}

__global__ void __launch_bounds__(256, 1) attn_mma_kernel(const int* __restrict__ amask)
{
    extern __shared__ __align__(16) __half smb[];
    __shared__ int am[64];

    __half* Qs = smb;
    __half* Kb = smb + ATT_Q_ELEMS;
    __half* Vb = Kb + ATT_K_ELEMS;

    const int tid  = threadIdx.x;
    const int lane = tid & 31;
    const int warp = tid >> 5;

    const int bid = blockIdx.x;
    const int qt  = 15 - (bid >> 4);
    const int h   = bid & 7;
    const int b   = (bid >> 3) & 1;
    const int qbase = qt * 128;
    const int jt_max = 2*qt + 1;

    // ---- Q resident load (single plane) ----
#pragma unroll
    for (int i = 0; i < 16; ++i) {
        const int idx = tid + i*256;
        const int r = idx >> 5, c = (idx & 31) << 3;
        cpa16(Qs + r*QS_STR + c,
              g_Qh + (size_t)(b*S_ + qbase + r)*D_ + h*HD_ + c);
    }
    CP_COMMIT();
    att_loadK(Kb, tid, b, 0, 0, 0);
    CP_COMMIT();

    float o[32][4];
#pragma unroll
    for (int i = 0; i < 32; ++i)
#pragma unroll
        for (int j = 0; j < 4; ++j) o[i][j] = 0.f;
    float m_lo = -1e30f, m_hi = -1e30f, l_lo = 0.f, l_hi = 0.f;

    const int rl = qbase + warp*16 + (lane >> 2);
    const int rh = rl + 8;

    for (int jt = 0; jt <= jt_max; ++jt) {
        const int kb = jt * 64;
        float s[8][4];
#pragma unroll
        for (int i = 0; i < 8; ++i)
#pragma unroll
            for (int j = 0; j < 4; ++j) s[i][j] = 0.f;

        for (int kk = 0; kk < 4; ++kk) {
            if (kk < 3) {
                att_loadK(Kb, tid, b, jt, kk + 1, (kk + 1) & 1);
                CP_COMMIT();
                CP_WAIT(1);
            } else {
                att_loadV(Vb, tid, b, jt, 0);
                CP_COMMIT();
                if (jt < jt_max) {
                    att_loadK(Kb, tid, b, jt + 1, 0, 0);
                    CP_COMMIT();
                    CP_WAIT(2);
                } else {
                    CP_WAIT(1);
                }
            }
            __syncthreads();
            if (kk == 0 && tid < 64) am[tid] = amask[b*S_ + kb + tid];

            const int buf = kk & 1;
#pragma unroll
            for (int ks = 0; ks < 4; ++ks) {
                unsigned qf[4];
                const unsigned qaddr_off = (warp*16 + (lane & 15))*QS_STR
                                         + kk*64 + ks*16 + ((lane >> 4) << 3);
                ldsm_x4(qf, sptr(Qs + qaddr_off));
#pragma unroll
                for (int nf2 = 0; nf2 < 4; ++nf2) {
                    unsigned kf[4];
                    const int koff = (ks*16 + (lane & 15))*KT_STR
                                   + nf2*16 + ((lane >> 4) << 3);
                    ldsm_x4t(kf, sptr(Kb + buf*64*KT_STR + koff));
                    mma_f16(s[nf2*2],   qf, kf);
                    mma_f16(s[nf2*2+1], qf, kf + 2);
                }
            }
            __syncthreads();
        }

#pragma unroll
        for (int nf = 0; nf < 8; ++nf) {
#pragma unroll
            for (int j = 0; j < 2; ++j) {
                const int cl = nf*8 + (lane & 3)*2 + j;
                const int cg = kb + cl;
                const bool bad = (am[cl] == 0);
                if (bad || cg > rl) s[nf][j]     = -1e30f;
                if (bad || cg > rh) s[nf][2 + j] = -1e30f;
            }
        }
        float ml = -1e30f, mh = -1e30f;
#pragma unroll
        for (int nf = 0; nf < 8; ++nf) {
            ml = fmaxf(ml, fmaxf(s[nf][0], s[nf][1]));
            mh = fmaxf(mh, fmaxf(s[nf][2], s[nf][3]));
        }
        ml = fmaxf(ml, __shfl_xor_sync(0xffffffffu, ml, 1));
        ml = fmaxf(ml, __shfl_xor_sync(0xffffffffu, ml, 2));
        mh = fmaxf(mh, __shfl_xor_sync(0xffffffffu, mh, 1));
        mh = fmaxf(mh, __shfl_xor_sync(0xffffffffu, mh, 2));

        const float mnl = fmaxf(m_lo, ml);
        const float mnh = fmaxf(m_hi, mh);
        const float al = ex2(m_lo - mnl);
        const float ah = ex2(m_hi - mnh);
        m_lo = mnl; m_hi = mnh;

        float suml = 0.f, sumh = 0.f;
#pragma unroll
        for (int nf = 0; nf < 8; ++nf) {
            s[nf][0] = ex2(s[nf][0] - mnl);  suml += s[nf][0];
            s[nf][1] = ex2(s[nf][1] - mnl);  suml += s[nf][1];
            s[nf][2] = ex2(s[nf][2] - mnh);  sumh += s[nf][2];
            s[nf][3] = ex2(s[nf][3] - mnh);  sumh += s[nf][3];
        }
        suml += __shfl_xor_sync(0xffffffffu, suml, 1);
        suml += __shfl_xor_sync(0xffffffffu, suml, 2);
        sumh += __shfl_xor_sync(0xffffffffu, sumh, 1);
        sumh += __shfl_xor_sync(0xffffffffu, sumh, 2);
        l_lo = l_lo*al + suml;
        l_hi = l_hi*ah + sumh;
#pragma unroll
        for (int nf = 0; nf < 32; ++nf) {
            o[nf][0] *= al; o[nf][1] *= al;
            o[nf][2] *= ah; o[nf][3] *= ah;
        }

        // P accum-frags -> fp16 A-frags (single plane)
        unsigned pf[4][4];
#pragma unroll
        for (int kk = 0; kk < 4; ++kk) {
            const int f0 = 2*kk, f1 = 2*kk + 1;
            pf[kk][0] = pack_h2(s[f0][0], s[f0][1]);
            pf[kk][1] = pack_h2(s[f0][2], s[f0][3]);
            pf[kk][2] = pack_h2(s[f1][0], s[f1][1]);
            pf[kk][3] = pack_h2(s[f1][2], s[f1][3]);
        }

        // ---- PV: half 0 ----
        if (jt < jt_max) { CP_WAIT(1); } else { CP_WAIT(0); }
        __syncthreads();
#pragma unroll
        for (int nf2 = 0; nf2 < 8; ++nf2) {
#pragma unroll
            for (int kk = 0; kk < 4; ++kk) {
                unsigned vf[4];
                const int voff = (kk*16 + (lane & 15))*VS_STR
                               + nf2*16 + ((lane >> 4) << 3);
                ldsm_x4t(vf, sptr(Vb + voff));
                mma_f16(o[nf2*2],   pf[kk], vf);
                mma_f16(o[nf2*2+1], pf[kk], vf + 2);
            }
        }
        __syncthreads();

        // ---- PV: half 1 ----
        att_loadV(Vb, tid, b, jt, 1);
        CP_COMMIT();
        CP_WAIT(0);
        __syncthreads();
#pragma unroll
        for (int nf2 = 0; nf2 < 8; ++nf2) {
#pragma unroll
            for (int kk = 0; kk < 4; ++kk) {
                unsigned vf[4];
                const int voff = (kk*16 + (lane & 15))*VS_STR
                               + nf2*16 + ((lane >> 4) << 3);
                ldsm_x4t(vf, sptr(Vb + voff));
                mma_f16(o[16 + nf2*2],   pf[kk], vf);
                mma_f16(o[16 + nf2*2+1], pf[kk], vf + 2);
            }
        }
        __syncthreads();
    }

    // ---- normalize, round to fp16, write AO for oproj ----
    const float invl = 1.f / l_lo;
    const float invh = 1.f / l_hi;
#pragma unroll
    for (int nf = 0; nf < 32; ++nf) {
        const int c = h*HD_ + nf*8 + (lane & 3)*2;
        *(unsigned*)&g_AOh[(size_t)(b*S_ + rl)*D_ + c] =
            pack_h2(o[nf][0]*invl, o[nf][1]*invl);
        *(unsigned*)&g_AOh[(size_t)(b*S_ + rh)*D_ + c] =
            pack_h2(o[nf][2]*invh, o[nf][3]*invh);
    }
}

// =====================================================================
extern "C" void kernel_launch(void* const* d_in, const int* in_sizes, int n_in,
                              void* d_out, int out_size)
{
    (void)in_sizes; (void)n_in; (void)out_size;
    const float* X   = (const float*)d_in[0];
    const int*   am  = (const int*)  d_in[1];
    const int*   pos = (const int*)  d_in[2];
    const float* Wq  = (const float*)d_in[3];
    const float* Wk  = (const float*)d_in[4];
    const float* Wv  = (const float*)d_in[5];
    const float* Wo  = (const float*)d_in[6];
    float* out = (float*)d_out;

    cudaFuncSetAttribute(tc4_gemm_kernel,
                         cudaFuncAttributeMaxDynamicSharedMemorySize, GEMM4_SMEM);
    cudaFuncSetAttribute(attn_mma_kernel,
                         cudaFuncAttributeMaxDynamicSharedMemorySize, ATT3_SMEM_BYTES);

    __half *Xh = 0, *Wh = 0, *WOh = 0, *AOh = 0;
    float *qkv = 0;
    cudaGetSymbolAddress((void**)&Xh,  g_Xh);
    cudaGetSymbolAddress((void**)&Wh,  g_Wh);
    cudaGetSymbolAddress((void**)&WOh, g_WOh);
    cudaGetSymbolAddress((void**)&AOh, g_AOh);
    cudaGetSymbolAddress((void**)&qkv, g_qkv);

    // 1. merged prep: X, W, Wo rounded fp16
    prep_kernel<<<(NX_ + NW_ + NWO_)/256, 256>>>(X, Wq, Wk, Wv, Wo);

    // 2. fused QKV projection (fp16): 128x128 tiles
    tc4_gemm_kernel<<<dim3(NQKV/128, (B_*S_)/128), 256, GEMM4_SMEM>>>(
        Xh, Wh, qkv, NQKV, D_);

    // 3. RoPE + fp16 prep of Q (scaled), K^T, V
    rope_split_kernel<<<B_*S_, 128>>>(pos);

    // 4. tensor-core flash attention (pure fp16, writes AOh)
    attn_mma_kernel<<<256, 256, ATT3_SMEM_BYTES>>>(am);

    // 5. output projection (fp16): 128x128 tiles
    tc4_gemm_kernel<<<dim3(D_/128, (B_*S_)/128), 256, GEMM4_SMEM>>>(
        AOh, WOh, out, D_, D_);
}